// round 8
// baseline (speedup 1.0000x reference)
#include <cuda_runtime.h>
#include <cuda_bf16.h>
#include <math.h>
#include <stdint.h>

#define BB 2
#define SS 2048
#define DMODEL 1024
#define NH 16
#define DH 64
#define MM (BB*SS)

// Scratch (device globals: allocation-guard safe).
__device__ float g_q[BB*NH*SS*DH];
__device__ float g_k[BB*NH*SS*DH];
__device__ float g_v[BB*NH*SS*DH];
// bf16 hi/lo converted operands: X at [0,4M), Wq/Wk/Wv/Wo at 4M+z*1M
__device__ __align__(16) __nv_bfloat16 g_cvh[8*1024*1024];
__device__ __align__(16) __nv_bfloat16 g_cvl[8*1024*1024];
// flash output (attention), packed bf16 hi/lo: [b, s, 1024] as bf16x2 words
__device__ __align__(16) uint32_t g_ah[MM*DMODEL/2];
__device__ __align__(16) uint32_t g_al[MM*DMODEL/2];

__device__ __forceinline__ float fex2(float x) {
    float y;
    asm("ex2.approx.ftz.f32 %0, %1;" : "=f"(y) : "f"(x));
    return y;
}
__device__ __forceinline__ uint32_t smem_u32(const void* p) {
    uint32_t a;
    asm("{ .reg .u64 t; cvta.to.shared.u64 t, %1; cvt.u32.u64 %0, t; }" : "=r"(a) : "l"(p));
    return a;
}
__device__ __forceinline__ void ldm4(uint32_t* r, uint32_t addr) {
    asm volatile("ldmatrix.sync.aligned.m8n8.x4.shared.b16 {%0,%1,%2,%3}, [%4];"
                 : "=r"(r[0]), "=r"(r[1]), "=r"(r[2]), "=r"(r[3]) : "r"(addr));
}
__device__ __forceinline__ void ldm4t(uint32_t* r, uint32_t addr) {
    asm volatile("ldmatrix.sync.aligned.m8n8.x4.trans.shared.b16 {%0,%1,%2,%3}, [%4];"
                 : "=r"(r[0]), "=r"(r[1]), "=r"(r[2]), "=r"(r[3]) : "r"(addr));
}
__device__ __forceinline__ void mma16816(float* c, const uint32_t* a, const uint32_t* b) {
    asm volatile(
        "mma.sync.aligned.m16n8k16.row.col.f32.bf16.bf16.f32 "
        "{%0,%1,%2,%3}, {%4,%5,%6,%7}, {%8,%9}, {%0,%1,%2,%3};"
        : "+f"(c[0]), "+f"(c[1]), "+f"(c[2]), "+f"(c[3])
        : "r"(a[0]), "r"(a[1]), "r"(a[2]), "r"(a[3]), "r"(b[0]), "r"(b[1]));
}
__device__ __forceinline__ uint32_t split2(float x, float y, uint32_t& lop) {
    __nv_bfloat162 h = __floats2bfloat162_rn(x, y);
    float rx = x - __bfloat162float(h.x);
    float ry = y - __bfloat162float(h.y);
    __nv_bfloat162 l = __floats2bfloat162_rn(rx, ry);
    lop = *reinterpret_cast<uint32_t*>(&l);
    return *reinterpret_cast<uint32_t*>(&h);
}
__device__ __forceinline__ void split8(const float4& a, const float4& b,
                                       uint4& hi, uint4& lo) {
    hi.x = split2(a.x, a.y, lo.x);
    hi.y = split2(a.z, a.w, lo.y);
    hi.z = split2(b.x, b.y, lo.z);
    hi.w = split2(b.z, b.w, lo.w);
}
__device__ __forceinline__ void cpa16(uint32_t d, const void* s) {
    asm volatile("cp.async.cg.shared.global [%0], [%1], 16;" :: "r"(d), "l"(s));
}

// ================= one-time fp32 -> bf16 hi/lo conversion ===================
__global__ __launch_bounds__(256) void conv_split(const float4* __restrict__ src,
                                                  int dst4, int n4)
{
    int i = blockIdx.x * blockDim.x + threadIdx.x;
    if (i >= n4) return;
    float4 v = src[i];
    uint32_t l0, l1;
    uint32_t h0 = split2(v.x, v.y, l0);
    uint32_t h1 = split2(v.z, v.w, l1);
    reinterpret_cast<uint2*>(g_cvh)[dst4 + i] = make_uint2(h0, h1);
    reinterpret_cast<uint2*>(g_cvl)[dst4 + i] = make_uint2(l0, l1);
}

// ====================== pipelined bf16 GEMM (cp.async) ======================
// C[M,N] = A[M,K] * W[N,K]^T with 3-term hi/lo accumulation, operands pre-split.
#define RS 80
#define OPB (128 * RS)        // 10240 B per operand tile
#define STB (4 * OPB)         // 40960 B per stage
#define SMTOT (2 * STB)       // 81920 B

template<bool QKV>
__global__ __launch_bounds__(256, 2) void gemm_bf16(
    const float* __restrict__ bias, float* __restrict__ Oout)
{
    extern __shared__ uint8_t sm[];
    const uint32_t sb = smem_u32(sm);
    const int tid = threadIdx.x;
    const int lane = tid & 31;
    const int wid = tid >> 5;
    const int warp_m = wid >> 2;
    const int warp_n = wid & 3;
    const int m0 = blockIdx.y * 128;
    const int n0 = blockIdx.x * 128;

    const __nv_bfloat16* Ah = QKV ? g_cvh : reinterpret_cast<const __nv_bfloat16*>(g_ah);
    const __nv_bfloat16* Al = QKV ? g_cvl : reinterpret_cast<const __nv_bfloat16*>(g_al);
    const size_t wOff = (size_t)4*1024*1024 + (size_t)(QKV ? blockIdx.z : 3u) * DMODEL * DMODEL;
    const __nv_bfloat16* Bh = g_cvh + wOff;
    const __nv_bfloat16* Bl = g_cvl + wOff;

    // copy assignment: row = tid>>1 (0..127), half = tid&1 (32B each)
    const int crow = tid >> 1;
    const int chalf = tid & 1;
    const __nv_bfloat16* aH = Ah + (size_t)(m0 + crow) * DMODEL + chalf * 16;
    const __nv_bfloat16* aL = Al + (size_t)(m0 + crow) * DMODEL + chalf * 16;
    const __nv_bfloat16* bH = Bh + (size_t)(n0 + crow) * DMODEL + chalf * 16;
    const __nv_bfloat16* bL = Bl + (size_t)(n0 + crow) * DMODEL + chalf * 16;
    const uint32_t dBase = sb + (uint32_t)(crow * RS + chalf * 32);

    // fragment addressing (validated layout, RSTRIDE=80)
    const int aRow = warp_m * 64 + (lane & 15);
    const uint32_t aByte = (uint32_t)((lane >> 4) * 16);
    const int bRow = warp_n * 32 + ((lane >> 4) * 8) + (lane & 7);
    const uint32_t bByte = (uint32_t)(((lane >> 3) & 1) * 16);

    float c[4][4][4];
    #pragma unroll
    for (int i = 0; i < 4; i++)
        #pragma unroll
        for (int j = 0; j < 4; j++)
            #pragma unroll
            for (int e = 0; e < 4; e++) c[i][j][e] = 0.0f;

    // prologue: stage 0 <- chunk 0
    {
        const uint32_t d = dBase;
        cpa16(d,             aH);      cpa16(d + 16,             aH + 8);
        cpa16(d + OPB,       aL);      cpa16(d + OPB + 16,       aL + 8);
        cpa16(d + 2*OPB,     bH);      cpa16(d + 2*OPB + 16,     bH + 8);
        cpa16(d + 3*OPB,     bL);      cpa16(d + 3*OPB + 16,     bL + 8);
        asm volatile("cp.async.commit_group;");
    }

    for (int ck = 0; ck < 32; ck++) {
        if (ck + 1 < 32) {
            const int k1 = (ck + 1) * 32;
            const uint32_t d = dBase + (uint32_t)(((ck + 1) & 1) * STB);
            cpa16(d,             aH + k1);  cpa16(d + 16,             aH + k1 + 8);
            cpa16(d + OPB,       aL + k1);  cpa16(d + OPB + 16,       aL + k1 + 8);
            cpa16(d + 2*OPB,     bH + k1);  cpa16(d + 2*OPB + 16,     bH + k1 + 8);
            cpa16(d + 3*OPB,     bL + k1);  cpa16(d + 3*OPB + 16,     bL + k1 + 8);
            asm volatile("cp.async.commit_group;");
            asm volatile("cp.async.wait_group 1;");
        } else {
            asm volatile("cp.async.wait_group 0;");
        }
        __syncthreads();

        const uint32_t sAh = sb + (uint32_t)((ck & 1) * STB);
        const uint32_t sAl = sAh + OPB;
        const uint32_t sBh = sAh + 2*OPB;
        const uint32_t sBl = sAh + 3*OPB;

        #pragma unroll
        for (int ks = 0; ks < 2; ks++) {
            const uint32_t kByte = (uint32_t)(ks * 32);
            uint32_t ah[4][4], bh[2][4], bl[2][4], al[4][4];
            #pragma unroll
            for (int i = 0; i < 4; i++)
                ldm4(ah[i], sAh + (uint32_t)((aRow + i * 16) * RS) + kByte + aByte);
            #pragma unroll
            for (int p = 0; p < 2; p++)
                ldm4(bh[p], sBh + (uint32_t)((bRow + p * 16) * RS) + kByte + bByte);
            #pragma unroll
            for (int i = 0; i < 4; i++)
                #pragma unroll
                for (int j = 0; j < 4; j++)
                    mma16816(c[i][j], ah[i], &bh[j >> 1][(j & 1) * 2]);
            #pragma unroll
            for (int p = 0; p < 2; p++)
                ldm4(bl[p], sBl + (uint32_t)((bRow + p * 16) * RS) + kByte + bByte);
            #pragma unroll
            for (int i = 0; i < 4; i++)
                #pragma unroll
                for (int j = 0; j < 4; j++)
                    mma16816(c[i][j], ah[i], &bl[j >> 1][(j & 1) * 2]);
            #pragma unroll
            for (int i = 0; i < 4; i++)
                ldm4(al[i], sAl + (uint32_t)((aRow + i * 16) * RS) + kByte + aByte);
            #pragma unroll
            for (int i = 0; i < 4; i++)
                #pragma unroll
                for (int j = 0; j < 4; j++)
                    mma16816(c[i][j], al[i], &bh[j >> 1][(j & 1) * 2]);
        }
        __syncthreads();
    }

    const int mrow = m0 + warp_m * 64 + (lane >> 2);
    const int ncol = n0 + warp_n * 32 + (lane & 3) * 2;
    #pragma unroll
    for (int i = 0; i < 4; i++) {
        #pragma unroll
        for (int half = 0; half < 2; half++) {
            const int m = mrow + i * 16 + half * 8;
            #pragma unroll
            for (int j = 0; j < 4; j++) {
                const int n = ncol + j * 8;
                float2 v;
                v.x = c[i][j][half * 2 + 0];
                v.y = c[i][j][half * 2 + 1];
                if (QKV) {
                    float* O = (blockIdx.z == 0) ? g_q : (blockIdx.z == 1) ? g_k : g_v;
                    const int b = m >> 11;
                    const int s = m & (SS - 1);
                    const int h = n >> 6, d = n & 63;
                    *reinterpret_cast<float2*>(
                        O + (((size_t)(b * NH + h)) * SS + s) * DH + d) = v;
                } else {
                    v.x += bias[n];
                    v.y += bias[n + 1];
                    *reinterpret_cast<float2*>(Oout + (size_t)m * DMODEL + n) = v;
                }
            }
        }
    }
}

// =========================== RoPE (unchanged) ===============================
__global__ __launch_bounds__(256) void rope_kernel()
{
    int idx = blockIdx.x * blockDim.x + threadIdx.x;
    int d  = idx & 31;
    int s  = (idx >> 5) & (SS - 1);
    int bh = idx >> 16;
    size_t base = ((size_t)bh * SS + s) * DH;

    const float nl2 = -13.2877123795494f / 32.0f;
    float inv_freq = exp2f((float)d * nl2);
    float ang = (float)s * inv_freq;
    float sn, cs;
    sincosf(ang, &sn, &cs);

    float q1 = g_q[base + d], q2 = g_q[base + d + 32];
    g_q[base + d]      = q1 * cs - q2 * sn;
    g_q[base + d + 32] = q2 * cs + q1 * sn;

    float k1 = g_k[base + d], k2 = g_k[base + d + 32];
    g_k[base + d]      = k1 * cs - k2 * sn;
    g_k[base + d + 32] = k2 * cs + k1 * sn;
}

// =========================== Flash attention (HMMA) =========================
#define VRS 144
#define FSM (64 * VRS)

__global__ __launch_bounds__(256) void flash_hmma()
{
    __shared__ uint8_t sm[4 * FSM];
    const uint32_t sb = smem_u32(sm);
    const uint32_t sKh = sb, sKl = sb + FSM, sVh = sb + 2*FSM, sVl = sb + 3*FSM;

    const int bh = blockIdx.x;
    const int qt = (gridDim.y - 1) - blockIdx.y;
    const int q0 = qt * 128;
    const int tid = threadIdx.x;
    const int lane = tid & 31;
    const int w = tid >> 5;
    const int b = bh >> 4;
    const int h = bh & 15;

    const float* Qb = g_q + (size_t)bh * SS * DH;
    const float* Kb = g_k + (size_t)bh * SS * DH;
    const float* Vb = g_v + (size_t)bh * SS * DH;

    const float sc = 0.125f * 1.44269504088896f;

    {
        const int row = tid >> 1;
        const int half = tid & 1;
        const float* Qp = Qb + (size_t)(q0 + row) * DH + half * 32;
        uint32_t dst = (uint32_t)(row * VRS + half * 64);
        #pragma unroll
        for (int i = 0; i < 4; i++) {
            float4 x = *reinterpret_cast<const float4*>(Qp + i * 8);
            float4 y = *reinterpret_cast<const float4*>(Qp + i * 8 + 4);
            x.x *= sc; x.y *= sc; x.z *= sc; x.w *= sc;
            y.x *= sc; y.y *= sc; y.z *= sc; y.w *= sc;
            uint4 hi, lo;
            split8(x, y, hi, lo);
            *reinterpret_cast<uint4*>(sm + dst + i * 16) = hi;
            *reinterpret_cast<uint4*>(sm + 2*FSM + dst + i * 16) = lo;
        }
    }
    __syncthreads();

    uint32_t qh[4][4], ql[4][4];
    {
        const uint32_t ra = (uint32_t)((w * 16 + (lane & 15)) * VRS) + (uint32_t)((lane >> 4) * 16);
        #pragma unroll
        for (int kb = 0; kb < 4; kb++) {
            ldm4(qh[kb], sKh + ra + (uint32_t)(kb * 32));
            ldm4(ql[kb], sVh + ra + (uint32_t)(kb * 32));
        }
    }

    float o[8][4];
    #pragma unroll
    for (int d = 0; d < 8; d++)
        #pragma unroll
        for (int e = 0; e < 4; e++) o[d][e] = 0.0f;
    float m0 = -INFINITY, m1 = -INFINITY, l0 = 0.0f, l1 = 0.0f;

    const uint32_t kAddrBase = (uint32_t)((lane & 7) * VRS + (lane >> 3) * 16);
    const uint32_t vAddrBase = (uint32_t)((lane & 15) * VRS) + (uint32_t)((lane >> 4) * 16);

    const int nkv = 2 * (qt + 1);
    for (int kt = 0; kt < nkv; kt++) {
        const int k0 = kt * 64;
        const int r = tid >> 2;
        const int cc = (tid & 3) * 16;
        float4 kr[4], vr[4];
        {
            const float* Kp = Kb + (size_t)(k0 + r) * DH + cc;
            const float* Vp = Vb + (size_t)(k0 + r) * DH + cc;
            #pragma unroll
            for (int i = 0; i < 4; i++) {
                kr[i] = *reinterpret_cast<const float4*>(Kp + i * 4);
                vr[i] = *reinterpret_cast<const float4*>(Vp + i * 4);
            }
        }
        __syncthreads();
        {
            uint32_t dst = (uint32_t)(r * VRS + (tid & 3) * 32);
            uint4 hi, lo;
            split8(kr[0], kr[1], hi, lo);
            *reinterpret_cast<uint4*>(sm + dst) = hi;
            *reinterpret_cast<uint4*>(sm + FSM + dst) = lo;
            split8(kr[2], kr[3], hi, lo);
            *reinterpret_cast<uint4*>(sm + dst + 16) = hi;
            *reinterpret_cast<uint4*>(sm + FSM + dst + 16) = lo;
            split8(vr[0], vr[1], hi, lo);
            *reinterpret_cast<uint4*>(sm + 2*FSM + dst) = hi;
            *reinterpret_cast<uint4*>(sm + 3*FSM + dst) = lo;
            split8(vr[2], vr[3], hi, lo);
            *reinterpret_cast<uint4*>(sm + 2*FSM + dst + 16) = hi;
            *reinterpret_cast<uint4*>(sm + 3*FSM + dst + 16) = lo;
        }
        __syncthreads();

        float s[8][4];
        #pragma unroll
        for (int jb = 0; jb < 8; jb++) {
            s[jb][0] = s[jb][1] = s[jb][2] = s[jb][3] = 0.0f;
            uint32_t khf[8], klf[8];
            const uint32_t ka = kAddrBase + (uint32_t)(jb * 8 * VRS);
            ldm4(&khf[0], sKh + ka);
            ldm4(&khf[4], sKh + ka + 64);
            ldm4(&klf[0], sKl + ka);
            ldm4(&klf[4], sKl + ka + 64);
            #pragma unroll
            for (int kb = 0; kb < 4; kb++) {
                mma16816(s[jb], qh[kb], &khf[kb * 2]);
                mma16816(s[jb], qh[kb], &klf[kb * 2]);
                mma16816(s[jb], ql[kb], &khf[kb * 2]);
            }
        }

        if (kt >= nkv - 2) {
            const int r0 = q0 + w * 16 + (lane >> 2);
            const int cb = k0 + (lane & 3) * 2;
            #pragma unroll
            for (int jb = 0; jb < 8; jb++) {
                const int c0 = cb + jb * 8;
                if (c0     > r0)     s[jb][0] = -INFINITY;
                if (c0 + 1 > r0)     s[jb][1] = -INFINITY;
                if (c0     > r0 + 8) s[jb][2] = -INFINITY;
                if (c0 + 1 > r0 + 8) s[jb][3] = -INFINITY;
            }
        }

        float nm0 = m0, nm1 = m1;
        #pragma unroll
        for (int jb = 0; jb < 8; jb++) {
            nm0 = fmaxf(nm0, fmaxf(s[jb][0], s[jb][1]));
            nm1 = fmaxf(nm1, fmaxf(s[jb][2], s[jb][3]));
        }
        nm0 = fmaxf(nm0, __shfl_xor_sync(0xFFFFFFFF, nm0, 1));
        nm0 = fmaxf(nm0, __shfl_xor_sync(0xFFFFFFFF, nm0, 2));
        nm1 = fmaxf(nm1, __shfl_xor_sync(0xFFFFFFFF, nm1, 1));
        nm1 = fmaxf(nm1, __shfl_xor_sync(0xFFFFFFFF, nm1, 2));
        const float c0 = fex2(m0 - nm0);
        const float c1 = fex2(m1 - nm1);
        m0 = nm0; m1 = nm1;

        float ps0 = 0.0f, ps1 = 0.0f;
        #pragma unroll
        for (int jb = 0; jb < 8; jb++) {
            s[jb][0] = fex2(s[jb][0] - nm0);
            s[jb][1] = fex2(s[jb][1] - nm0);
            s[jb][2] = fex2(s[jb][2] - nm1);
            s[jb][3] = fex2(s[jb][3] - nm1);
            ps0 += s[jb][0] + s[jb][1];
            ps1 += s[jb][2] + s[jb][3];
        }
        ps0 += __shfl_xor_sync(0xFFFFFFFF, ps0, 1);
        ps0 += __shfl_xor_sync(0xFFFFFFFF, ps0, 2);
        ps1 += __shfl_xor_sync(0xFFFFFFFF, ps1, 1);
        ps1 += __shfl_xor_sync(0xFFFFFFFF, ps1, 2);
        l0 = l0 * c0 + ps0;
        l1 = l1 * c1 + ps1;
        #pragma unroll
        for (int d = 0; d < 8; d++) {
            o[d][0] *= c0; o[d][1] *= c0;
            o[d][2] *= c1; o[d][3] *= c1;
        }

        #pragma unroll
        for (int kb = 0; kb < 4; kb++) {
            uint32_t ph[4], pl[4];
            ph[0] = split2(s[2*kb][0],   s[2*kb][1],   pl[0]);
            ph[1] = split2(s[2*kb][2],   s[2*kb][3],   pl[1]);
            ph[2] = split2(s[2*kb+1][0], s[2*kb+1][1], pl[2]);
            ph[3] = split2(s[2*kb+1][2], s[2*kb+1][3], pl[3]);
            const uint32_t va = vAddrBase + (uint32_t)(kb * 16 * VRS);
            #pragma unroll
            for (int dbp = 0; dbp < 4; dbp++) {
                uint32_t vh[4], vl[4];
                ldm4t(vh, sVh + va + (uint32_t)(dbp * 32));
                ldm4t(vl, sVl + va + (uint32_t)(dbp * 32));
                mma16816(o[dbp*2],     ph, &vh[0]);
                mma16816(o[dbp*2],     pl, &vh[0]);
                mma16816(o[dbp*2],     ph, &vl[0]);
                mma16816(o[dbp*2 + 1], ph, &vh[2]);
                mma16816(o[dbp*2 + 1], pl, &vh[2]);
                mma16816(o[dbp*2 + 1], ph, &vl[2]);
            }
        }
    }

    // epilogue: normalize, split to bf16 hi/lo, write packed words
    const float i0 = 1.0f / l0;
    const float i1 = 1.0f / l1;
    const int r0 = q0 + w * 16 + (lane >> 2);
    const uint32_t ro = (uint32_t)(b * SS + r0) * (DMODEL/2) + (uint32_t)(h * (DH/2) + (lane & 3));
    #pragma unroll
    for (int d = 0; d < 8; d++) {
        uint32_t lo0, lo1;
        uint32_t h0 = split2(o[d][0] * i0, o[d][1] * i0, lo0);
        uint32_t h1 = split2(o[d][2] * i1, o[d][3] * i1, lo1);
        g_ah[ro + d * 4] = h0;
        g_al[ro + d * 4] = lo0;
        g_ah[ro + 8 * (DMODEL/2) + d * 4] = h1;
        g_al[ro + 8 * (DMODEL/2) + d * 4] = lo1;
    }
}

// ---------------------------------------------------------------------------
extern "C" void kernel_launch(void* const* d_in, const int* in_sizes, int n_in,
                              void* d_out, int out_size)
{
    const float* X  = (const float*)d_in[0];
    const float* Wq = (const float*)d_in[1];
    const float* Wk = (const float*)d_in[2];
    const float* Wv = (const float*)d_in[3];
    const float* Wo = (const float*)d_in[4];
    const float* bo = (const float*)d_in[5];
    float* out = (float*)d_out;

    cudaFuncSetAttribute(gemm_bf16<true>,  cudaFuncAttributeMaxDynamicSharedMemorySize, SMTOT);
    cudaFuncSetAttribute(gemm_bf16<false>, cudaFuncAttributeMaxDynamicSharedMemorySize, SMTOT);

    // 0. one-time fp32 -> bf16 hi/lo conversion (X + 4 weights)
    conv_split<<<4096, 256>>>((const float4*)X,  0,       1048576);
    conv_split<<<1024, 256>>>((const float4*)Wq, 1048576, 262144);
    conv_split<<<1024, 256>>>((const float4*)Wk, 1310720, 262144);
    conv_split<<<1024, 256>>>((const float4*)Wv, 1572864, 262144);
    conv_split<<<1024, 256>>>((const float4*)Wo, 1835008, 262144);
    // 1. QKV projections (pipelined bf16 HMMA) -> head-major scratch
    gemm_bf16<true><<<dim3(8, 32, 3), 256, SMTOT>>>(nullptr, nullptr);
    // 2. RoPE in-place on Q, K
    rope_kernel<<<(BB*NH*SS*32) / 256, 256>>>();
    // 3. Causal flash attention (HMMA) -> packed bf16 hi/lo attention output
    flash_hmma<<<dim3(32, 16), 256>>>();
    // 4. Output projection + bias -> d_out
    gemm_bf16<false><<<dim3(8, 32, 1), 256, SMTOT>>>(bo, out);
}

// round 9
// speedup vs baseline: 1.0363x; 1.0363x over previous
#include <cuda_runtime.h>
#include <cuda_bf16.h>
#include <math.h>
#include <stdint.h>

#define BB 2
#define SS 2048
#define DMODEL 1024
#define NH 16
#define DH 64
#define MM (BB*SS)

// Scratch (device globals: allocation-guard safe).
__device__ float g_q[BB*NH*SS*DH];
__device__ float g_k[BB*NH*SS*DH];
__device__ float g_v[BB*NH*SS*DH];
__device__ float g_attn[MM*DMODEL];

__device__ __forceinline__ float fex2(float x) {
    float y;
    asm("ex2.approx.ftz.f32 %0, %1;" : "=f"(y) : "f"(x));
    return y;
}
__device__ __forceinline__ uint32_t smem_u32(const void* p) {
    uint32_t a;
    asm("{ .reg .u64 t; cvta.to.shared.u64 t, %1; cvt.u32.u64 %0, t; }" : "=r"(a) : "l"(p));
    return a;
}
__device__ __forceinline__ void ldm4(uint32_t* r, uint32_t addr) {
    asm volatile("ldmatrix.sync.aligned.m8n8.x4.shared.b16 {%0,%1,%2,%3}, [%4];"
                 : "=r"(r[0]), "=r"(r[1]), "=r"(r[2]), "=r"(r[3]) : "r"(addr));
}
__device__ __forceinline__ void ldm4t(uint32_t* r, uint32_t addr) {
    asm volatile("ldmatrix.sync.aligned.m8n8.x4.trans.shared.b16 {%0,%1,%2,%3}, [%4];"
                 : "=r"(r[0]), "=r"(r[1]), "=r"(r[2]), "=r"(r[3]) : "r"(addr));
}
__device__ __forceinline__ void mma16816(float* c, const uint32_t* a, const uint32_t* b) {
    asm volatile(
        "mma.sync.aligned.m16n8k16.row.col.f32.bf16.bf16.f32 "
        "{%0,%1,%2,%3}, {%4,%5,%6,%7}, {%8,%9}, {%0,%1,%2,%3};"
        : "+f"(c[0]), "+f"(c[1]), "+f"(c[2]), "+f"(c[3])
        : "r"(a[0]), "r"(a[1]), "r"(a[2]), "r"(a[3]), "r"(b[0]), "r"(b[1]));
}
__device__ __forceinline__ uint32_t split2(float x, float y, uint32_t& lop) {
    __nv_bfloat162 h = __floats2bfloat162_rn(x, y);
    float rx = x - __bfloat162float(h.x);
    float ry = y - __bfloat162float(h.y);
    __nv_bfloat162 l = __floats2bfloat162_rn(rx, ry);
    lop = *reinterpret_cast<uint32_t*>(&l);
    return *reinterpret_cast<uint32_t*>(&h);
}
__device__ __forceinline__ void split8(const float4& a, const float4& b,
                                       uint4& hi, uint4& lo) {
    hi.x = split2(a.x, a.y, lo.x);
    hi.y = split2(a.z, a.w, lo.y);
    hi.z = split2(b.x, b.y, lo.z);
    hi.w = split2(b.z, b.w, lo.w);
}

// ============== pipelined 3-term bf16 GEMM (double-buffered SMEM) ==========
// C[M,N] = A[M,K] * W[N,K]^T.  One barrier per K-chunk; LDG[ck+1] overlaps
// MMA[ck]; STS[ck+1] goes to the buffer not being read.
#define RS 80
#define OPB (128 * RS)        // 10240 B per operand tile
#define STB (4 * OPB)         // 40960 B per stage
#define SMTOT (2 * STB)       // 81920 B

template<bool QKV>
__global__ __launch_bounds__(256) void gemm_hmma(
    const float* __restrict__ A,
    const float* __restrict__ W0, const float* __restrict__ W1,
    const float* __restrict__ W2,
    const float* __restrict__ bias, float* __restrict__ Oout)
{
    extern __shared__ uint8_t sm[];
    const uint32_t sb = smem_u32(sm);

    const int tid = threadIdx.x;
    const int lane = tid & 31;
    const int wid = tid >> 5;
    const int warp_m = wid >> 2;
    const int warp_n = wid & 3;

    const float* Ap = QKV ? A : g_attn;
    const float* W = W0;
    if (QKV) {
        if (blockIdx.z == 1) W = W1;
        else if (blockIdx.z == 2) W = W2;
    }
    const int m0 = blockIdx.y * 128;
    const int n0 = blockIdx.x * 128;

    // load/store assignment (validated R7 layout)
    const int lrow = tid >> 2;       // 0..63 (rows lrow, lrow+64)
    const int c8 = tid & 3;          // 8-float column group
    const uint32_t o0 = (uint32_t)(lrow * RS + c8 * 16);
    const uint32_t o1 = (uint32_t)((lrow + 64) * RS + c8 * 16);
    const float* aP0 = Ap + (size_t)(m0 + lrow) * DMODEL + c8 * 8;
    const float* aP1 = Ap + (size_t)(m0 + lrow + 64) * DMODEL + c8 * 8;
    const float* bP0 = W + (size_t)(n0 + lrow) * DMODEL + c8 * 8;
    const float* bP1 = W + (size_t)(n0 + lrow + 64) * DMODEL + c8 * 8;

    // fragment addressing (validated layout, RS=80)
    const int aRow = warp_m * 64 + (lane & 15);
    const uint32_t aByte = (uint32_t)((lane >> 4) * 16);
    const int bRow = warp_n * 32 + ((lane >> 4) * 8) + (lane & 7);
    const uint32_t bByte = (uint32_t)(((lane >> 3) & 1) * 16);

    float c[4][4][4];
    #pragma unroll
    for (int i = 0; i < 4; i++)
        #pragma unroll
        for (int j = 0; j < 4; j++)
            #pragma unroll
            for (int e = 0; e < 4; e++) c[i][j][e] = 0.0f;

    float4 av[4], bv[4];
    // prologue: load chunk 0, split, store to stage 0
    {
        av[0] = *(const float4*)aP0;       av[1] = *(const float4*)(aP0 + 4);
        av[2] = *(const float4*)aP1;       av[3] = *(const float4*)(aP1 + 4);
        bv[0] = *(const float4*)bP0;       bv[1] = *(const float4*)(bP0 + 4);
        bv[2] = *(const float4*)bP1;       bv[3] = *(const float4*)(bP1 + 4);
        uint4 hi, lo;
        split8(av[0], av[1], hi, lo);
        *(uint4*)(sm + o0) = hi;                 *(uint4*)(sm + OPB + o0) = lo;
        split8(av[2], av[3], hi, lo);
        *(uint4*)(sm + o1) = hi;                 *(uint4*)(sm + OPB + o1) = lo;
        split8(bv[0], bv[1], hi, lo);
        *(uint4*)(sm + 2*OPB + o0) = hi;         *(uint4*)(sm + 3*OPB + o0) = lo;
        split8(bv[2], bv[3], hi, lo);
        *(uint4*)(sm + 2*OPB + o1) = hi;         *(uint4*)(sm + 3*OPB + o1) = lo;
    }
    __syncthreads();

    for (int ck = 0; ck < 32; ck++) {
        // 1. issue next chunk's LDGs (latency hidden under this chunk's MMAs)
        if (ck + 1 < 32) {
            const int k1 = (ck + 1) * 32;
            av[0] = *(const float4*)(aP0 + k1);  av[1] = *(const float4*)(aP0 + k1 + 4);
            av[2] = *(const float4*)(aP1 + k1);  av[3] = *(const float4*)(aP1 + k1 + 4);
            bv[0] = *(const float4*)(bP0 + k1);  bv[1] = *(const float4*)(bP0 + k1 + 4);
            bv[2] = *(const float4*)(bP1 + k1);  bv[3] = *(const float4*)(bP1 + k1 + 4);
        }

        // 2. MMA on current stage
        const uint32_t sAh = sb + (uint32_t)((ck & 1) * STB);
        const uint32_t sAl = sAh + OPB;
        const uint32_t sBh = sAh + 2*OPB;
        const uint32_t sBl = sAh + 3*OPB;
        #pragma unroll
        for (int ks = 0; ks < 2; ks++) {
            const uint32_t kByte = (uint32_t)(ks * 32);
            uint32_t ah[4][4], bh[2][4], bl[2][4], al[4][4];
            #pragma unroll
            for (int i = 0; i < 4; i++)
                ldm4(ah[i], sAh + (uint32_t)((aRow + i * 16) * RS) + kByte + aByte);
            #pragma unroll
            for (int p = 0; p < 2; p++)
                ldm4(bh[p], sBh + (uint32_t)((bRow + p * 16) * RS) + kByte + bByte);
            #pragma unroll
            for (int i = 0; i < 4; i++)
                #pragma unroll
                for (int j = 0; j < 4; j++)
                    mma16816(c[i][j], ah[i], &bh[j >> 1][(j & 1) * 2]);
            #pragma unroll
            for (int p = 0; p < 2; p++)
                ldm4(bl[p], sBl + (uint32_t)((bRow + p * 16) * RS) + kByte + bByte);
            #pragma unroll
            for (int i = 0; i < 4; i++)
                #pragma unroll
                for (int j = 0; j < 4; j++)
                    mma16816(c[i][j], ah[i], &bl[j >> 1][(j & 1) * 2]);
            #pragma unroll
            for (int i = 0; i < 4; i++)
                ldm4(al[i], sAl + (uint32_t)((aRow + i * 16) * RS) + kByte + aByte);
            #pragma unroll
            for (int i = 0; i < 4; i++)
                #pragma unroll
                for (int j = 0; j < 4; j++)
                    mma16816(c[i][j], al[i], &bh[j >> 1][(j & 1) * 2]);
        }

        // 3. split + store next chunk into the other stage, then ONE barrier
        if (ck + 1 < 32) {
            uint8_t* dst = sm + ((ck + 1) & 1) * STB;
            uint4 hi, lo;
            split8(av[0], av[1], hi, lo);
            *(uint4*)(dst + o0) = hi;               *(uint4*)(dst + OPB + o0) = lo;
            split8(av[2], av[3], hi, lo);
            *(uint4*)(dst + o1) = hi;               *(uint4*)(dst + OPB + o1) = lo;
            split8(bv[0], bv[1], hi, lo);
            *(uint4*)(dst + 2*OPB + o0) = hi;       *(uint4*)(dst + 3*OPB + o0) = lo;
            split8(bv[2], bv[3], hi, lo);
            *(uint4*)(dst + 2*OPB + o1) = hi;       *(uint4*)(dst + 3*OPB + o1) = lo;
            __syncthreads();
        }
    }

    const int mrow = m0 + warp_m * 64 + (lane >> 2);
    const int ncol = n0 + warp_n * 32 + (lane & 3) * 2;
    #pragma unroll
    for (int i = 0; i < 4; i++) {
        #pragma unroll
        for (int half = 0; half < 2; half++) {
            const int m = mrow + i * 16 + half * 8;
            #pragma unroll
            for (int j = 0; j < 4; j++) {
                const int n = ncol + j * 8;
                float2 v;
                v.x = c[i][j][half * 2 + 0];
                v.y = c[i][j][half * 2 + 1];
                if (QKV) {
                    float* O = (blockIdx.z == 0) ? g_q : (blockIdx.z == 1) ? g_k : g_v;
                    const int b = m >> 11;
                    const int s = m & (SS - 1);
                    const int h = n >> 6, d = n & 63;
                    *reinterpret_cast<float2*>(
                        O + (((size_t)(b * NH + h)) * SS + s) * DH + d) = v;
                } else {
                    v.x += bias[n];
                    v.y += bias[n + 1];
                    *reinterpret_cast<float2*>(Oout + (size_t)m * DMODEL + n) = v;
                }
            }
        }
    }
}

// =========================== RoPE (unchanged) ===============================
__global__ __launch_bounds__(256) void rope_kernel()
{
    int idx = blockIdx.x * blockDim.x + threadIdx.x;
    int d  = idx & 31;
    int s  = (idx >> 5) & (SS - 1);
    int bh = idx >> 16;
    size_t base = ((size_t)bh * SS + s) * DH;

    const float nl2 = -13.2877123795494f / 32.0f;
    float inv_freq = exp2f((float)d * nl2);
    float ang = (float)s * inv_freq;
    float sn, cs;
    sincosf(ang, &sn, &cs);

    float q1 = g_q[base + d], q2 = g_q[base + d + 32];
    g_q[base + d]      = q1 * cs - q2 * sn;
    g_q[base + d + 32] = q2 * cs + q1 * sn;

    float k1 = g_k[base + d], k2 = g_k[base + d + 32];
    g_k[base + d]      = k1 * cs - k2 * sn;
    g_k[base + d + 32] = k2 * cs + k1 * sn;
}

// ================== Flash attention (HMMA, validated R7) ====================
#define VRS 144
#define FSM (64 * VRS)

__global__ __launch_bounds__(256) void flash_hmma()
{
    __shared__ uint8_t sm[4 * FSM];
    const uint32_t sb = smem_u32(sm);
    const uint32_t sKh = sb, sKl = sb + FSM, sVh = sb + 2*FSM, sVl = sb + 3*FSM;

    const int bh = blockIdx.x;
    const int qt = (gridDim.y - 1) - blockIdx.y;
    const int q0 = qt * 128;
    const int tid = threadIdx.x;
    const int lane = tid & 31;
    const int w = tid >> 5;
    const int b = bh >> 4;
    const int h = bh & 15;

    const float* Qb = g_q + (size_t)bh * SS * DH;
    const float* Kb = g_k + (size_t)bh * SS * DH;
    const float* Vb = g_v + (size_t)bh * SS * DH;

    const float sc = 0.125f * 1.44269504088896f;

    {
        const int row = tid >> 1;
        const int half = tid & 1;
        const float* Qp = Qb + (size_t)(q0 + row) * DH + half * 32;
        uint32_t dst = (uint32_t)(row * VRS + half * 64);
        #pragma unroll
        for (int i = 0; i < 4; i++) {
            float4 x = *reinterpret_cast<const float4*>(Qp + i * 8);
            float4 y = *reinterpret_cast<const float4*>(Qp + i * 8 + 4);
            x.x *= sc; x.y *= sc; x.z *= sc; x.w *= sc;
            y.x *= sc; y.y *= sc; y.z *= sc; y.w *= sc;
            uint4 hi, lo;
            split8(x, y, hi, lo);
            *reinterpret_cast<uint4*>(sm + dst + i * 16) = hi;
            *reinterpret_cast<uint4*>(sm + 2*FSM + dst + i * 16) = lo;
        }
    }
    __syncthreads();

    uint32_t qh[4][4], ql[4][4];
    {
        const uint32_t ra = (uint32_t)((w * 16 + (lane & 15)) * VRS) + (uint32_t)((lane >> 4) * 16);
        #pragma unroll
        for (int kb = 0; kb < 4; kb++) {
            ldm4(qh[kb], sKh + ra + (uint32_t)(kb * 32));
            ldm4(ql[kb], sVh + ra + (uint32_t)(kb * 32));
        }
    }

    float o[8][4];
    #pragma unroll
    for (int d = 0; d < 8; d++)
        #pragma unroll
        for (int e = 0; e < 4; e++) o[d][e] = 0.0f;
    float m0 = -INFINITY, m1 = -INFINITY, l0 = 0.0f, l1 = 0.0f;

    const uint32_t kAddrBase = (uint32_t)((lane & 7) * VRS + (lane >> 3) * 16);
    const uint32_t vAddrBase = (uint32_t)((lane & 15) * VRS) + (uint32_t)((lane >> 4) * 16);

    const int nkv = 2 * (qt + 1);
    for (int kt = 0; kt < nkv; kt++) {
        const int k0 = kt * 64;
        const int r = tid >> 2;
        const int cc = (tid & 3) * 16;
        float4 kr[4], vr[4];
        {
            const float* Kp = Kb + (size_t)(k0 + r) * DH + cc;
            const float* Vp = Vb + (size_t)(k0 + r) * DH + cc;
            #pragma unroll
            for (int i = 0; i < 4; i++) {
                kr[i] = *reinterpret_cast<const float4*>(Kp + i * 4);
                vr[i] = *reinterpret_cast<const float4*>(Vp + i * 4);
            }
        }
        __syncthreads();
        {
            uint32_t dst = (uint32_t)(r * VRS + (tid & 3) * 32);
            uint4 hi, lo;
            split8(kr[0], kr[1], hi, lo);
            *reinterpret_cast<uint4*>(sm + dst) = hi;
            *reinterpret_cast<uint4*>(sm + FSM + dst) = lo;
            split8(kr[2], kr[3], hi, lo);
            *reinterpret_cast<uint4*>(sm + dst + 16) = hi;
            *reinterpret_cast<uint4*>(sm + FSM + dst + 16) = lo;
            split8(vr[0], vr[1], hi, lo);
            *reinterpret_cast<uint4*>(sm + 2*FSM + dst) = hi;
            *reinterpret_cast<uint4*>(sm + 3*FSM + dst) = lo;
            split8(vr[2], vr[3], hi, lo);
            *reinterpret_cast<uint4*>(sm + 2*FSM + dst + 16) = hi;
            *reinterpret_cast<uint4*>(sm + 3*FSM + dst + 16) = lo;
        }
        __syncthreads();

        float s[8][4];
        #pragma unroll
        for (int jb = 0; jb < 8; jb++) {
            s[jb][0] = s[jb][1] = s[jb][2] = s[jb][3] = 0.0f;
            uint32_t khf[8], klf[8];
            const uint32_t ka = kAddrBase + (uint32_t)(jb * 8 * VRS);
            ldm4(&khf[0], sKh + ka);
            ldm4(&khf[4], sKh + ka + 64);
            ldm4(&klf[0], sKl + ka);
            ldm4(&klf[4], sKl + ka + 64);
            #pragma unroll
            for (int kb = 0; kb < 4; kb++) {
                mma16816(s[jb], qh[kb], &khf[kb * 2]);
                mma16816(s[jb], qh[kb], &klf[kb * 2]);
                mma16816(s[jb], ql[kb], &khf[kb * 2]);
            }
        }

        if (kt >= nkv - 2) {
            const int r0 = q0 + w * 16 + (lane >> 2);
            const int cb = k0 + (lane & 3) * 2;
            #pragma unroll
            for (int jb = 0; jb < 8; jb++) {
                const int c0 = cb + jb * 8;
                if (c0     > r0)     s[jb][0] = -INFINITY;
                if (c0 + 1 > r0)     s[jb][1] = -INFINITY;
                if (c0     > r0 + 8) s[jb][2] = -INFINITY;
                if (c0 + 1 > r0 + 8) s[jb][3] = -INFINITY;
            }
        }

        float nm0 = m0, nm1 = m1;
        #pragma unroll
        for (int jb = 0; jb < 8; jb++) {
            nm0 = fmaxf(nm0, fmaxf(s[jb][0], s[jb][1]));
            nm1 = fmaxf(nm1, fmaxf(s[jb][2], s[jb][3]));
        }
        nm0 = fmaxf(nm0, __shfl_xor_sync(0xFFFFFFFF, nm0, 1));
        nm0 = fmaxf(nm0, __shfl_xor_sync(0xFFFFFFFF, nm0, 2));
        nm1 = fmaxf(nm1, __shfl_xor_sync(0xFFFFFFFF, nm1, 1));
        nm1 = fmaxf(nm1, __shfl_xor_sync(0xFFFFFFFF, nm1, 2));
        const float c0 = fex2(m0 - nm0);
        const float c1 = fex2(m1 - nm1);
        m0 = nm0; m1 = nm1;

        float ps0 = 0.0f, ps1 = 0.0f;
        #pragma unroll
        for (int jb = 0; jb < 8; jb++) {
            s[jb][0] = fex2(s[jb][0] - nm0);
            s[jb][1] = fex2(s[jb][1] - nm0);
            s[jb][2] = fex2(s[jb][2] - nm1);
            s[jb][3] = fex2(s[jb][3] - nm1);
            ps0 += s[jb][0] + s[jb][1];
            ps1 += s[jb][2] + s[jb][3];
        }
        ps0 += __shfl_xor_sync(0xFFFFFFFF, ps0, 1);
        ps0 += __shfl_xor_sync(0xFFFFFFFF, ps0, 2);
        ps1 += __shfl_xor_sync(0xFFFFFFFF, ps1, 1);
        ps1 += __shfl_xor_sync(0xFFFFFFFF, ps1, 2);
        l0 = l0 * c0 + ps0;
        l1 = l1 * c1 + ps1;
        #pragma unroll
        for (int d = 0; d < 8; d++) {
            o[d][0] *= c0; o[d][1] *= c0;
            o[d][2] *= c1; o[d][3] *= c1;
        }

        #pragma unroll
        for (int kb = 0; kb < 4; kb++) {
            uint32_t ph[4], pl[4];
            ph[0] = split2(s[2*kb][0],   s[2*kb][1],   pl[0]);
            ph[1] = split2(s[2*kb][2],   s[2*kb][3],   pl[1]);
            ph[2] = split2(s[2*kb+1][0], s[2*kb+1][1], pl[2]);
            ph[3] = split2(s[2*kb+1][2], s[2*kb+1][3], pl[3]);
            const uint32_t va = vAddrBase + (uint32_t)(kb * 16 * VRS);
            #pragma unroll
            for (int dbp = 0; dbp < 4; dbp++) {
                uint32_t vh[4], vl[4];
                ldm4t(vh, sVh + va + (uint32_t)(dbp * 32));
                ldm4t(vl, sVl + va + (uint32_t)(dbp * 32));
                mma16816(o[dbp*2],     ph, &vh[0]);
                mma16816(o[dbp*2],     pl, &vh[0]);
                mma16816(o[dbp*2],     ph, &vl[0]);
                mma16816(o[dbp*2 + 1], ph, &vh[2]);
                mma16816(o[dbp*2 + 1], pl, &vh[2]);
                mma16816(o[dbp*2 + 1], ph, &vl[2]);
            }
        }
    }

    const float i0 = 1.0f / l0;
    const float i1 = 1.0f / l1;
    const int r0 = q0 + w * 16 + (lane >> 2);
    float* out0 = g_attn + ((size_t)(b * SS + r0)) * DMODEL + h * DH + (lane & 3) * 2;
    float* out1 = out0 + (size_t)8 * DMODEL;
    #pragma unroll
    for (int d = 0; d < 8; d++) {
        float2 v0, v1;
        v0.x = o[d][0] * i0; v0.y = o[d][1] * i0;
        v1.x = o[d][2] * i1; v1.y = o[d][3] * i1;
        *reinterpret_cast<float2*>(out0 + d * 8) = v0;
        *reinterpret_cast<float2*>(out1 + d * 8) = v1;
    }
}

// ---------------------------------------------------------------------------
extern "C" void kernel_launch(void* const* d_in, const int* in_sizes, int n_in,
                              void* d_out, int out_size)
{
    const float* X  = (const float*)d_in[0];
    const float* Wq = (const float*)d_in[1];
    const float* Wk = (const float*)d_in[2];
    const float* Wv = (const float*)d_in[3];
    const float* Wo = (const float*)d_in[4];
    const float* bo = (const float*)d_in[5];
    float* out = (float*)d_out;

    cudaFuncSetAttribute(gemm_hmma<true>,  cudaFuncAttributeMaxDynamicSharedMemorySize, SMTOT);
    cudaFuncSetAttribute(gemm_hmma<false>, cudaFuncAttributeMaxDynamicSharedMemorySize, SMTOT);

    // 1. QKV projections (pipelined bf16 HMMA) -> head-major scratch
    gemm_hmma<true><<<dim3(8, 32, 3), 256, SMTOT>>>(X, Wq, Wk, Wv, nullptr, nullptr);
    // 2. RoPE in-place on Q, K
    rope_kernel<<<(BB*NH*SS*32) / 256, 256>>>();
    // 3. Causal flash attention (HMMA) -> g_attn [b, s, h*dh]
    flash_hmma<<<dim3(32, 16), 256>>>();
    // 4. Output projection + bias -> d_out
    gemm_hmma<false><<<dim3(8, 32, 1), 256, SMTOT>>>(nullptr, Wo, nullptr, nullptr, bo, out);
}

// round 10
// speedup vs baseline: 1.1236x; 1.0842x over previous
#include <cuda_runtime.h>
#include <cuda_bf16.h>
#include <math.h>
#include <stdint.h>

#define BB 2
#define SS 2048
#define DMODEL 1024
#define NH 16
#define DH 64
#define MM (BB*SS)

// Scratch (device globals: allocation-guard safe).
__device__ float g_q[BB*NH*SS*DH];
__device__ float g_k[BB*NH*SS*DH];
__device__ float g_v[BB*NH*SS*DH];
__device__ float g_attn[MM*DMODEL];

__device__ __forceinline__ float fex2(float x) {
    float y;
    asm("ex2.approx.ftz.f32 %0, %1;" : "=f"(y) : "f"(x));
    return y;
}
__device__ __forceinline__ uint32_t smem_u32(const void* p) {
    uint32_t a;
    asm("{ .reg .u64 t; cvta.to.shared.u64 t, %1; cvt.u32.u64 %0, t; }" : "=r"(a) : "l"(p));
    return a;
}
__device__ __forceinline__ void ldm4(uint32_t* r, uint32_t addr) {
    asm volatile("ldmatrix.sync.aligned.m8n8.x4.shared.b16 {%0,%1,%2,%3}, [%4];"
                 : "=r"(r[0]), "=r"(r[1]), "=r"(r[2]), "=r"(r[3]) : "r"(addr));
}
__device__ __forceinline__ void ldm4t(uint32_t* r, uint32_t addr) {
    asm volatile("ldmatrix.sync.aligned.m8n8.x4.trans.shared.b16 {%0,%1,%2,%3}, [%4];"
                 : "=r"(r[0]), "=r"(r[1]), "=r"(r[2]), "=r"(r[3]) : "r"(addr));
}
__device__ __forceinline__ void mma16816(float* c, const uint32_t* a, const uint32_t* b) {
    asm volatile(
        "mma.sync.aligned.m16n8k16.row.col.f32.bf16.bf16.f32 "
        "{%0,%1,%2,%3}, {%4,%5,%6,%7}, {%8,%9}, {%0,%1,%2,%3};"
        : "+f"(c[0]), "+f"(c[1]), "+f"(c[2]), "+f"(c[3])
        : "r"(a[0]), "r"(a[1]), "r"(a[2]), "r"(a[3]), "r"(b[0]), "r"(b[1]));
}
__device__ __forceinline__ uint32_t split2(float x, float y, uint32_t& lop) {
    __nv_bfloat162 h = __floats2bfloat162_rn(x, y);
    float rx = x - __bfloat162float(h.x);
    float ry = y - __bfloat162float(h.y);
    __nv_bfloat162 l = __floats2bfloat162_rn(rx, ry);
    lop = *reinterpret_cast<uint32_t*>(&l);
    return *reinterpret_cast<uint32_t*>(&h);
}
__device__ __forceinline__ void split8(const float4& a, const float4& b,
                                       uint4& hi, uint4& lo) {
    hi.x = split2(a.x, a.y, lo.x);
    hi.y = split2(a.z, a.w, lo.y);
    hi.z = split2(b.x, b.y, lo.z);
    hi.w = split2(b.z, b.w, lo.w);
}

// ========== 3-term bf16 GEMM: 128x128 CTA, 4 warps of 64x64 ================
// C[M,N] = A[M,K] * W[N,K]^T. Same loop structure as the validated R7 kernel;
// bigger warp tiles cut LDSM bytes per MMA by 33% (smem-BW was the wall).
#define RS 80
#define OPB (128 * RS)   // 10240 B per operand tile; 4*OPB = 40960 B static

template<bool QKV>
__global__ __launch_bounds__(128, 2) void gemm_hmma(
    const float* __restrict__ A,
    const float* __restrict__ W0, const float* __restrict__ W1,
    const float* __restrict__ W2,
    const float* __restrict__ bias, float* __restrict__ Oout)
{
    __shared__ uint8_t sm[4 * OPB];
    const uint32_t sb = smem_u32(sm);
    const uint32_t sAh = sb, sAl = sb + OPB, sBh = sb + 2*OPB, sBl = sb + 3*OPB;

    const int tid = threadIdx.x;
    const int lane = tid & 31;
    const int wid = tid >> 5;           // 0..3
    const int warp_m = wid >> 1;        // 0..1 -> 64 rows
    const int warp_n = wid & 1;         // 0..1 -> 64 cols

    const float* Ap = QKV ? A : g_attn;
    const float* W = W0;
    if (QKV) {
        if (blockIdx.z == 1) W = W1;
        else if (blockIdx.z == 2) W = W2;
    }
    const int m0 = blockIdx.y * 128;
    const int n0 = blockIdx.x * 128;

    // loader: rows lrow+32p (p=0..3), cols c8*8..+7; STS conflict-free (16B/lane)
    const int lrow = tid >> 2;          // 0..31
    const int c8 = tid & 3;             // 0..3

    // fragment addressing (validated pattern, RS=80)
    const int aRow = warp_m * 64 + (lane & 15);
    const uint32_t aByte = (uint32_t)((lane >> 4) * 16);
    const int bRow = warp_n * 64 + ((lane >> 4) * 8) + (lane & 7);
    const uint32_t bByte = (uint32_t)(((lane >> 3) & 1) * 16);

    float c[4][8][4];
    #pragma unroll
    for (int i = 0; i < 4; i++)
        #pragma unroll
        for (int j = 0; j < 8; j++)
            #pragma unroll
            for (int e = 0; e < 4; e++) c[i][j][e] = 0.0f;

    for (int ck = 0; ck < 32; ck++) {
        const int k0 = ck * 32;
        // GMEM loads (before the barrier; other CTA's MMAs cover latency)
        float4 av[4][2], bv[4][2];
        #pragma unroll
        for (int p = 0; p < 4; p++) {
            const float* aP = Ap + (size_t)(m0 + lrow + 32*p) * DMODEL + k0 + c8 * 8;
            const float* bP = W  + (size_t)(n0 + lrow + 32*p) * DMODEL + k0 + c8 * 8;
            av[p][0] = *(const float4*)aP;  av[p][1] = *(const float4*)(aP + 4);
            bv[p][0] = *(const float4*)bP;  bv[p][1] = *(const float4*)(bP + 4);
        }

        __syncthreads();  // previous iteration's ldmatrix reads done

        #pragma unroll
        for (int p = 0; p < 4; p++) {
            const uint32_t o = (uint32_t)((lrow + 32*p) * RS + c8 * 16);
            uint4 hi, lo;
            split8(av[p][0], av[p][1], hi, lo);
            *(uint4*)(sm + o) = hi;            *(uint4*)(sm + OPB + o) = lo;
            split8(bv[p][0], bv[p][1], hi, lo);
            *(uint4*)(sm + 2*OPB + o) = hi;    *(uint4*)(sm + 3*OPB + o) = lo;
        }
        __syncthreads();

        #pragma unroll
        for (int ks = 0; ks < 2; ks++) {
            const uint32_t kByte = (uint32_t)(ks * 32);
            uint32_t ah[4][4], bh[4][4], bl[4][4], al[4][4];
            #pragma unroll
            for (int i = 0; i < 4; i++)
                ldm4(ah[i], sAh + (uint32_t)((aRow + i * 16) * RS) + kByte + aByte);
            #pragma unroll
            for (int nb = 0; nb < 4; nb++)
                ldm4(bh[nb], sBh + (uint32_t)((bRow + nb * 16) * RS) + kByte + bByte);
            // product 1: Ah * Bh
            #pragma unroll
            for (int i = 0; i < 4; i++)
                #pragma unroll
                for (int j = 0; j < 8; j++)
                    mma16816(c[i][j], ah[i], &bh[j >> 1][(j & 1) * 2]);
            // product 2: Ah * Bl
            #pragma unroll
            for (int nb = 0; nb < 4; nb++)
                ldm4(bl[nb], sBl + (uint32_t)((bRow + nb * 16) * RS) + kByte + bByte);
            #pragma unroll
            for (int i = 0; i < 4; i++)
                #pragma unroll
                for (int j = 0; j < 8; j++)
                    mma16816(c[i][j], ah[i], &bl[j >> 1][(j & 1) * 2]);
            // product 3: Al * Bh
            #pragma unroll
            for (int i = 0; i < 4; i++)
                ldm4(al[i], sAl + (uint32_t)((aRow + i * 16) * RS) + kByte + aByte);
            #pragma unroll
            for (int i = 0; i < 4; i++)
                #pragma unroll
                for (int j = 0; j < 8; j++)
                    mma16816(c[i][j], al[i], &bh[j >> 1][(j & 1) * 2]);
        }
    }

    // epilogue: warp owns 64x64; thread owns (lane>>2 [+8], (lane&3)*2 +j*8)
    const int mrow = m0 + warp_m * 64 + (lane >> 2);
    const int ncol = n0 + warp_n * 64 + (lane & 3) * 2;
    #pragma unroll
    for (int i = 0; i < 4; i++) {
        #pragma unroll
        for (int half = 0; half < 2; half++) {
            const int m = mrow + i * 16 + half * 8;
            #pragma unroll
            for (int j = 0; j < 8; j++) {
                const int n = ncol + j * 8;
                float2 v;
                v.x = c[i][j][half * 2 + 0];
                v.y = c[i][j][half * 2 + 1];
                if (QKV) {
                    float* O = (blockIdx.z == 0) ? g_q : (blockIdx.z == 1) ? g_k : g_v;
                    const int b = m >> 11;
                    const int s = m & (SS - 1);
                    const int h = n >> 6, d = n & 63;
                    *reinterpret_cast<float2*>(
                        O + (((size_t)(b * NH + h)) * SS + s) * DH + d) = v;
                } else {
                    v.x += bias[n];
                    v.y += bias[n + 1];
                    *reinterpret_cast<float2*>(Oout + (size_t)m * DMODEL + n) = v;
                }
            }
        }
    }
}

// =========================== RoPE (unchanged) ===============================
__global__ __launch_bounds__(256) void rope_kernel()
{
    int idx = blockIdx.x * blockDim.x + threadIdx.x;
    int d  = idx & 31;
    int s  = (idx >> 5) & (SS - 1);
    int bh = idx >> 16;
    size_t base = ((size_t)bh * SS + s) * DH;

    const float nl2 = -13.2877123795494f / 32.0f;
    float inv_freq = exp2f((float)d * nl2);
    float ang = (float)s * inv_freq;
    float sn, cs;
    sincosf(ang, &sn, &cs);

    float q1 = g_q[base + d], q2 = g_q[base + d + 32];
    g_q[base + d]      = q1 * cs - q2 * sn;
    g_q[base + d + 32] = q2 * cs + q1 * sn;

    float k1 = g_k[base + d], k2 = g_k[base + d + 32];
    g_k[base + d]      = k1 * cs - k2 * sn;
    g_k[base + d + 32] = k2 * cs + k1 * sn;
}

// ================== Flash attention (HMMA, validated R7) ====================
#define VRS 144
#define FSM (64 * VRS)

__global__ __launch_bounds__(256) void flash_hmma()
{
    __shared__ uint8_t sm[4 * FSM];
    const uint32_t sb = smem_u32(sm);
    const uint32_t sKh = sb, sKl = sb + FSM, sVh = sb + 2*FSM, sVl = sb + 3*FSM;

    const int bh = blockIdx.x;
    const int qt = (gridDim.y - 1) - blockIdx.y;
    const int q0 = qt * 128;
    const int tid = threadIdx.x;
    const int lane = tid & 31;
    const int w = tid >> 5;
    const int b = bh >> 4;
    const int h = bh & 15;

    const float* Qb = g_q + (size_t)bh * SS * DH;
    const float* Kb = g_k + (size_t)bh * SS * DH;
    const float* Vb = g_v + (size_t)bh * SS * DH;

    const float sc = 0.125f * 1.44269504088896f;

    {
        const int row = tid >> 1;
        const int half = tid & 1;
        const float* Qp = Qb + (size_t)(q0 + row) * DH + half * 32;
        uint32_t dst = (uint32_t)(row * VRS + half * 64);
        #pragma unroll
        for (int i = 0; i < 4; i++) {
            float4 x = *reinterpret_cast<const float4*>(Qp + i * 8);
            float4 y = *reinterpret_cast<const float4*>(Qp + i * 8 + 4);
            x.x *= sc; x.y *= sc; x.z *= sc; x.w *= sc;
            y.x *= sc; y.y *= sc; y.z *= sc; y.w *= sc;
            uint4 hi, lo;
            split8(x, y, hi, lo);
            *reinterpret_cast<uint4*>(sm + dst + i * 16) = hi;
            *reinterpret_cast<uint4*>(sm + 2*FSM + dst + i * 16) = lo;
        }
    }
    __syncthreads();

    uint32_t qh[4][4], ql[4][4];
    {
        const uint32_t ra = (uint32_t)((w * 16 + (lane & 15)) * VRS) + (uint32_t)((lane >> 4) * 16);
        #pragma unroll
        for (int kb = 0; kb < 4; kb++) {
            ldm4(qh[kb], sKh + ra + (uint32_t)(kb * 32));
            ldm4(ql[kb], sVh + ra + (uint32_t)(kb * 32));
        }
    }

    float o[8][4];
    #pragma unroll
    for (int d = 0; d < 8; d++)
        #pragma unroll
        for (int e = 0; e < 4; e++) o[d][e] = 0.0f;
    float m0 = -INFINITY, m1 = -INFINITY, l0 = 0.0f, l1 = 0.0f;

    const uint32_t kAddrBase = (uint32_t)((lane & 7) * VRS + (lane >> 3) * 16);
    const uint32_t vAddrBase = (uint32_t)((lane & 15) * VRS) + (uint32_t)((lane >> 4) * 16);

    const int nkv = 2 * (qt + 1);
    for (int kt = 0; kt < nkv; kt++) {
        const int k0 = kt * 64;
        const int r = tid >> 2;
        const int cc = (tid & 3) * 16;
        float4 kr[4], vr[4];
        {
            const float* Kp = Kb + (size_t)(k0 + r) * DH + cc;
            const float* Vp = Vb + (size_t)(k0 + r) * DH + cc;
            #pragma unroll
            for (int i = 0; i < 4; i++) {
                kr[i] = *reinterpret_cast<const float4*>(Kp + i * 4);
                vr[i] = *reinterpret_cast<const float4*>(Vp + i * 4);
            }
        }
        __syncthreads();
        {
            uint32_t dst = (uint32_t)(r * VRS + (tid & 3) * 32);
            uint4 hi, lo;
            split8(kr[0], kr[1], hi, lo);
            *reinterpret_cast<uint4*>(sm + dst) = hi;
            *reinterpret_cast<uint4*>(sm + FSM + dst) = lo;
            split8(kr[2], kr[3], hi, lo);
            *reinterpret_cast<uint4*>(sm + dst + 16) = hi;
            *reinterpret_cast<uint4*>(sm + FSM + dst + 16) = lo;
            split8(vr[0], vr[1], hi, lo);
            *reinterpret_cast<uint4*>(sm + 2*FSM + dst) = hi;
            *reinterpret_cast<uint4*>(sm + 3*FSM + dst) = lo;
            split8(vr[2], vr[3], hi, lo);
            *reinterpret_cast<uint4*>(sm + 2*FSM + dst + 16) = hi;
            *reinterpret_cast<uint4*>(sm + 3*FSM + dst + 16) = lo;
        }
        __syncthreads();

        float s[8][4];
        #pragma unroll
        for (int jb = 0; jb < 8; jb++) {
            s[jb][0] = s[jb][1] = s[jb][2] = s[jb][3] = 0.0f;
            uint32_t khf[8], klf[8];
            const uint32_t ka = kAddrBase + (uint32_t)(jb * 8 * VRS);
            ldm4(&khf[0], sKh + ka);
            ldm4(&khf[4], sKh + ka + 64);
            ldm4(&klf[0], sKl + ka);
            ldm4(&klf[4], sKl + ka + 64);
            #pragma unroll
            for (int kb = 0; kb < 4; kb++) {
                mma16816(s[jb], qh[kb], &khf[kb * 2]);
                mma16816(s[jb], qh[kb], &klf[kb * 2]);
                mma16816(s[jb], ql[kb], &khf[kb * 2]);
            }
        }

        if (kt >= nkv - 2) {
            const int r0 = q0 + w * 16 + (lane >> 2);
            const int cb = k0 + (lane & 3) * 2;
            #pragma unroll
            for (int jb = 0; jb < 8; jb++) {
                const int c0 = cb + jb * 8;
                if (c0     > r0)     s[jb][0] = -INFINITY;
                if (c0 + 1 > r0)     s[jb][1] = -INFINITY;
                if (c0     > r0 + 8) s[jb][2] = -INFINITY;
                if (c0 + 1 > r0 + 8) s[jb][3] = -INFINITY;
            }
        }

        float nm0 = m0, nm1 = m1;
        #pragma unroll
        for (int jb = 0; jb < 8; jb++) {
            nm0 = fmaxf(nm0, fmaxf(s[jb][0], s[jb][1]));
            nm1 = fmaxf(nm1, fmaxf(s[jb][2], s[jb][3]));
        }
        nm0 = fmaxf(nm0, __shfl_xor_sync(0xFFFFFFFF, nm0, 1));
        nm0 = fmaxf(nm0, __shfl_xor_sync(0xFFFFFFFF, nm0, 2));
        nm1 = fmaxf(nm1, __shfl_xor_sync(0xFFFFFFFF, nm1, 1));
        nm1 = fmaxf(nm1, __shfl_xor_sync(0xFFFFFFFF, nm1, 2));
        const float c0 = fex2(m0 - nm0);
        const float c1 = fex2(m1 - nm1);
        m0 = nm0; m1 = nm1;

        float ps0 = 0.0f, ps1 = 0.0f;
        #pragma unroll
        for (int jb = 0; jb < 8; jb++) {
            s[jb][0] = fex2(s[jb][0] - nm0);
            s[jb][1] = fex2(s[jb][1] - nm0);
            s[jb][2] = fex2(s[jb][2] - nm1);
            s[jb][3] = fex2(s[jb][3] - nm1);
            ps0 += s[jb][0] + s[jb][1];
            ps1 += s[jb][2] + s[jb][3];
        }
        ps0 += __shfl_xor_sync(0xFFFFFFFF, ps0, 1);
        ps0 += __shfl_xor_sync(0xFFFFFFFF, ps0, 2);
        ps1 += __shfl_xor_sync(0xFFFFFFFF, ps1, 1);
        ps1 += __shfl_xor_sync(0xFFFFFFFF, ps1, 2);
        l0 = l0 * c0 + ps0;
        l1 = l1 * c1 + ps1;
        #pragma unroll
        for (int d = 0; d < 8; d++) {
            o[d][0] *= c0; o[d][1] *= c0;
            o[d][2] *= c1; o[d][3] *= c1;
        }

        #pragma unroll
        for (int kb = 0; kb < 4; kb++) {
            uint32_t ph[4], pl[4];
            ph[0] = split2(s[2*kb][0],   s[2*kb][1],   pl[0]);
            ph[1] = split2(s[2*kb][2],   s[2*kb][3],   pl[1]);
            ph[2] = split2(s[2*kb+1][0], s[2*kb+1][1], pl[2]);
            ph[3] = split2(s[2*kb+1][2], s[2*kb+1][3], pl[3]);
            const uint32_t va = vAddrBase + (uint32_t)(kb * 16 * VRS);
            #pragma unroll
            for (int dbp = 0; dbp < 4; dbp++) {
                uint32_t vh[4], vl[4];
                ldm4t(vh, sVh + va + (uint32_t)(dbp * 32));
                ldm4t(vl, sVl + va + (uint32_t)(dbp * 32));
                mma16816(o[dbp*2],     ph, &vh[0]);
                mma16816(o[dbp*2],     pl, &vh[0]);
                mma16816(o[dbp*2],     ph, &vl[0]);
                mma16816(o[dbp*2 + 1], ph, &vh[2]);
                mma16816(o[dbp*2 + 1], pl, &vh[2]);
                mma16816(o[dbp*2 + 1], ph, &vl[2]);
            }
        }
    }

    const float i0 = 1.0f / l0;
    const float i1 = 1.0f / l1;
    const int r0 = q0 + w * 16 + (lane >> 2);
    float* out0 = g_attn + ((size_t)(b * SS + r0)) * DMODEL + h * DH + (lane & 3) * 2;
    float* out1 = out0 + (size_t)8 * DMODEL;
    #pragma unroll
    for (int d = 0; d < 8; d++) {
        float2 v0, v1;
        v0.x = o[d][0] * i0; v0.y = o[d][1] * i0;
        v1.x = o[d][2] * i1; v1.y = o[d][3] * i1;
        *reinterpret_cast<float2*>(out0 + d * 8) = v0;
        *reinterpret_cast<float2*>(out1 + d * 8) = v1;
    }
}

// ---------------------------------------------------------------------------
extern "C" void kernel_launch(void* const* d_in, const int* in_sizes, int n_in,
                              void* d_out, int out_size)
{
    const float* X  = (const float*)d_in[0];
    const float* Wq = (const float*)d_in[1];
    const float* Wk = (const float*)d_in[2];
    const float* Wv = (const float*)d_in[3];
    const float* Wo = (const float*)d_in[4];
    const float* bo = (const float*)d_in[5];
    float* out = (float*)d_out;

    // 1. QKV projections (bf16 HMMA, 64x64 warp tiles) -> head-major scratch
    gemm_hmma<true><<<dim3(8, 32, 3), 128>>>(X, Wq, Wk, Wv, nullptr, nullptr);
    // 2. RoPE in-place on Q, K
    rope_kernel<<<(BB*NH*SS*32) / 256, 256>>>();
    // 3. Causal flash attention (HMMA) -> g_attn [b, s, h*dh]
    flash_hmma<<<dim3(32, 16), 256>>>();
    // 4. Output projection + bias -> d_out
    gemm_hmma<false><<<dim3(8, 32, 1), 128>>>(nullptr, Wo, nullptr, nullptr, bo, out);
}

// round 11
// speedup vs baseline: 1.2699x; 1.1303x over previous
#include <cuda_runtime.h>
#include <cuda_bf16.h>
#include <cuda_fp16.h>
#include <math.h>
#include <stdint.h>

#define BB 2
#define SS 2048
#define DMODEL 1024
#define NH 16
#define DH 64
#define MM (BB*SS)

// Scratch (device globals: allocation-guard safe).
__device__ float g_q[BB*NH*SS*DH];
__device__ float g_k[BB*NH*SS*DH];
__device__ float g_v[BB*NH*SS*DH];
__device__ float g_attn[MM*DMODEL];

__device__ __forceinline__ float fex2(float x) {
    float y;
    asm("ex2.approx.ftz.f32 %0, %1;" : "=f"(y) : "f"(x));
    return y;
}
__device__ __forceinline__ uint32_t smem_u32(const void* p) {
    uint32_t a;
    asm("{ .reg .u64 t; cvta.to.shared.u64 t, %1; cvt.u32.u64 %0, t; }" : "=r"(a) : "l"(p));
    return a;
}
__device__ __forceinline__ void ldm4(uint32_t* r, uint32_t addr) {
    asm volatile("ldmatrix.sync.aligned.m8n8.x4.shared.b16 {%0,%1,%2,%3}, [%4];"
                 : "=r"(r[0]), "=r"(r[1]), "=r"(r[2]), "=r"(r[3]) : "r"(addr));
}
__device__ __forceinline__ void ldm4t(uint32_t* r, uint32_t addr) {
    asm volatile("ldmatrix.sync.aligned.m8n8.x4.trans.shared.b16 {%0,%1,%2,%3}, [%4];"
                 : "=r"(r[0]), "=r"(r[1]), "=r"(r[2]), "=r"(r[3]) : "r"(addr));
}
// bf16 mma (flash kernel)
__device__ __forceinline__ void mma16816(float* c, const uint32_t* a, const uint32_t* b) {
    asm volatile(
        "mma.sync.aligned.m16n8k16.row.col.f32.bf16.bf16.f32 "
        "{%0,%1,%2,%3}, {%4,%5,%6,%7}, {%8,%9}, {%0,%1,%2,%3};"
        : "+f"(c[0]), "+f"(c[1]), "+f"(c[2]), "+f"(c[3])
        : "r"(a[0]), "r"(a[1]), "r"(a[2]), "r"(a[3]), "r"(b[0]), "r"(b[1]));
}
// fp16 mma (projection GEMMs)
__device__ __forceinline__ void mma16816h(float* c, const uint32_t* a, const uint32_t* b) {
    asm volatile(
        "mma.sync.aligned.m16n8k16.row.col.f32.f16.f16.f32 "
        "{%0,%1,%2,%3}, {%4,%5,%6,%7}, {%8,%9}, {%0,%1,%2,%3};"
        : "+f"(c[0]), "+f"(c[1]), "+f"(c[2]), "+f"(c[3])
        : "r"(a[0]), "r"(a[1]), "r"(a[2]), "r"(a[3]), "r"(b[0]), "r"(b[1]));
}
// bf16 split helpers (flash)
__device__ __forceinline__ uint32_t split2(float x, float y, uint32_t& lop) {
    __nv_bfloat162 h = __floats2bfloat162_rn(x, y);
    float rx = x - __bfloat162float(h.x);
    float ry = y - __bfloat162float(h.y);
    __nv_bfloat162 l = __floats2bfloat162_rn(rx, ry);
    lop = *reinterpret_cast<uint32_t*>(&l);
    return *reinterpret_cast<uint32_t*>(&h);
}
__device__ __forceinline__ void split8(const float4& a, const float4& b,
                                       uint4& hi, uint4& lo) {
    hi.x = split2(a.x, a.y, lo.x);
    hi.y = split2(a.z, a.w, lo.y);
    hi.z = split2(b.x, b.y, lo.z);
    hi.w = split2(b.z, b.w, lo.w);
}
// fp16 helpers (GEMM)
__device__ __forceinline__ uint32_t pack2h(float x, float y) {
    __half2 h = __floats2half2_rn(x, y);
    return *reinterpret_cast<uint32_t*>(&h);
}
__device__ __forceinline__ uint32_t split2h(float x, float y, uint32_t& lop) {
    __half2 h = __floats2half2_rn(x, y);
    float rx = x - __half2float(__low2half(h));
    float ry = y - __half2float(__high2half(h));
    __half2 l = __floats2half2_rn(rx, ry);
    lop = *reinterpret_cast<uint32_t*>(&l);
    return *reinterpret_cast<uint32_t*>(&h);
}

// ======== fp16 2-term GEMM: 128x128 CTA, 4 warps of 64x64 (R10 frame) =======
// C = A * W^T,  C ≈ fp16(A)·(Wh + Wl).  MMA count 2/3 of the bf16 3-term.
#define RS 80
#define OPB (128 * RS)   // 10240 B per operand tile; 3*OPB = 30720 B static

template<bool QKV>
__global__ __launch_bounds__(128, 2) void gemm_hmma(
    const float* __restrict__ A,
    const float* __restrict__ W0, const float* __restrict__ W1,
    const float* __restrict__ W2,
    const float* __restrict__ bias, float* __restrict__ Oout)
{
    __shared__ uint8_t sm[3 * OPB];
    const uint32_t sb = smem_u32(sm);
    const uint32_t sAh = sb, sBh = sb + OPB, sBl = sb + 2*OPB;

    const int tid = threadIdx.x;
    const int lane = tid & 31;
    const int wid = tid >> 5;           // 0..3
    const int warp_m = wid >> 1;        // 0..1 -> 64 rows
    const int warp_n = wid & 1;         // 0..1 -> 64 cols

    const float* Ap = QKV ? A : g_attn;
    const float* W = W0;
    if (QKV) {
        if (blockIdx.z == 1) W = W1;
        else if (blockIdx.z == 2) W = W2;
    }
    const int m0 = blockIdx.y * 128;
    const int n0 = blockIdx.x * 128;

    const int lrow = tid >> 2;          // 0..31
    const int c8 = tid & 3;             // 0..3

    const int aRow = warp_m * 64 + (lane & 15);
    const uint32_t aByte = (uint32_t)((lane >> 4) * 16);
    const int bRow = warp_n * 64 + ((lane >> 4) * 8) + (lane & 7);
    const uint32_t bByte = (uint32_t)(((lane >> 3) & 1) * 16);

    float c[4][8][4];
    #pragma unroll
    for (int i = 0; i < 4; i++)
        #pragma unroll
        for (int j = 0; j < 8; j++)
            #pragma unroll
            for (int e = 0; e < 4; e++) c[i][j][e] = 0.0f;

    for (int ck = 0; ck < 32; ck++) {
        const int k0 = ck * 32;
        float4 av[4][2], bv[4][2];
        #pragma unroll
        for (int p = 0; p < 4; p++) {
            const float* aP = Ap + (size_t)(m0 + lrow + 32*p) * DMODEL + k0 + c8 * 8;
            const float* bP = W  + (size_t)(n0 + lrow + 32*p) * DMODEL + k0 + c8 * 8;
            av[p][0] = *(const float4*)aP;  av[p][1] = *(const float4*)(aP + 4);
            bv[p][0] = *(const float4*)bP;  bv[p][1] = *(const float4*)(bP + 4);
        }

        __syncthreads();  // previous iteration's ldmatrix reads done

        #pragma unroll
        for (int p = 0; p < 4; p++) {
            const uint32_t o = (uint32_t)((lrow + 32*p) * RS + c8 * 16);
            // A: fp16 hi only
            uint4 ha;
            ha.x = pack2h(av[p][0].x, av[p][0].y);
            ha.y = pack2h(av[p][0].z, av[p][0].w);
            ha.z = pack2h(av[p][1].x, av[p][1].y);
            ha.w = pack2h(av[p][1].z, av[p][1].w);
            *(uint4*)(sm + o) = ha;
            // B: fp16 hi + residual
            uint4 hb, lb;
            hb.x = split2h(bv[p][0].x, bv[p][0].y, lb.x);
            hb.y = split2h(bv[p][0].z, bv[p][0].w, lb.y);
            hb.z = split2h(bv[p][1].x, bv[p][1].y, lb.z);
            hb.w = split2h(bv[p][1].z, bv[p][1].w, lb.w);
            *(uint4*)(sm + OPB + o) = hb;
            *(uint4*)(sm + 2*OPB + o) = lb;
        }
        __syncthreads();

        #pragma unroll
        for (int ks = 0; ks < 2; ks++) {
            const uint32_t kByte = (uint32_t)(ks * 32);
            uint32_t ah[4][4], bh[4][4], bl[4][4];
            #pragma unroll
            for (int i = 0; i < 4; i++)
                ldm4(ah[i], sAh + (uint32_t)((aRow + i * 16) * RS) + kByte + aByte);
            #pragma unroll
            for (int nb = 0; nb < 4; nb++)
                ldm4(bh[nb], sBh + (uint32_t)((bRow + nb * 16) * RS) + kByte + bByte);
            // product 1: Ah * Bh
            #pragma unroll
            for (int i = 0; i < 4; i++)
                #pragma unroll
                for (int j = 0; j < 8; j++)
                    mma16816h(c[i][j], ah[i], &bh[j >> 1][(j & 1) * 2]);
            // product 2: Ah * Bl
            #pragma unroll
            for (int nb = 0; nb < 4; nb++)
                ldm4(bl[nb], sBl + (uint32_t)((bRow + nb * 16) * RS) + kByte + bByte);
            #pragma unroll
            for (int i = 0; i < 4; i++)
                #pragma unroll
                for (int j = 0; j < 8; j++)
                    mma16816h(c[i][j], ah[i], &bl[j >> 1][(j & 1) * 2]);
        }
    }

    const int mrow = m0 + warp_m * 64 + (lane >> 2);
    const int ncol = n0 + warp_n * 64 + (lane & 3) * 2;
    #pragma unroll
    for (int i = 0; i < 4; i++) {
        #pragma unroll
        for (int half = 0; half < 2; half++) {
            const int m = mrow + i * 16 + half * 8;
            #pragma unroll
            for (int j = 0; j < 8; j++) {
                const int n = ncol + j * 8;
                float2 v;
                v.x = c[i][j][half * 2 + 0];
                v.y = c[i][j][half * 2 + 1];
                if (QKV) {
                    float* O = (blockIdx.z == 0) ? g_q : (blockIdx.z == 1) ? g_k : g_v;
                    const int b = m >> 11;
                    const int s = m & (SS - 1);
                    const int h = n >> 6, d = n & 63;
                    *reinterpret_cast<float2*>(
                        O + (((size_t)(b * NH + h)) * SS + s) * DH + d) = v;
                } else {
                    v.x += bias[n];
                    v.y += bias[n + 1];
                    *reinterpret_cast<float2*>(Oout + (size_t)m * DMODEL + n) = v;
                }
            }
        }
    }
}

// =========================== RoPE (unchanged) ===============================
__global__ __launch_bounds__(256) void rope_kernel()
{
    int idx = blockIdx.x * blockDim.x + threadIdx.x;
    int d  = idx & 31;
    int s  = (idx >> 5) & (SS - 1);
    int bh = idx >> 16;
    size_t base = ((size_t)bh * SS + s) * DH;

    const float nl2 = -13.2877123795494f / 32.0f;
    float inv_freq = exp2f((float)d * nl2);
    float ang = (float)s * inv_freq;
    float sn, cs;
    sincosf(ang, &sn, &cs);

    float q1 = g_q[base + d], q2 = g_q[base + d + 32];
    g_q[base + d]      = q1 * cs - q2 * sn;
    g_q[base + d + 32] = q2 * cs + q1 * sn;

    float k1 = g_k[base + d], k2 = g_k[base + d + 32];
    g_k[base + d]      = k1 * cs - k2 * sn;
    g_k[base + d + 32] = k2 * cs + k1 * sn;
}

// ================== Flash attention (HMMA, validated; unchanged) ============
#define VRS 144
#define FSM (64 * VRS)

__global__ __launch_bounds__(256) void flash_hmma()
{
    __shared__ uint8_t sm[4 * FSM];
    const uint32_t sb = smem_u32(sm);
    const uint32_t sKh = sb, sKl = sb + FSM, sVh = sb + 2*FSM, sVl = sb + 3*FSM;

    const int bh = blockIdx.x;
    const int qt = (gridDim.y - 1) - blockIdx.y;
    const int q0 = qt * 128;
    const int tid = threadIdx.x;
    const int lane = tid & 31;
    const int w = tid >> 5;
    const int b = bh >> 4;
    const int h = bh & 15;

    const float* Qb = g_q + (size_t)bh * SS * DH;
    const float* Kb = g_k + (size_t)bh * SS * DH;
    const float* Vb = g_v + (size_t)bh * SS * DH;

    const float sc = 0.125f * 1.44269504088896f;

    {
        const int row = tid >> 1;
        const int half = tid & 1;
        const float* Qp = Qb + (size_t)(q0 + row) * DH + half * 32;
        uint32_t dst = (uint32_t)(row * VRS + half * 64);
        #pragma unroll
        for (int i = 0; i < 4; i++) {
            float4 x = *reinterpret_cast<const float4*>(Qp + i * 8);
            float4 y = *reinterpret_cast<const float4*>(Qp + i * 8 + 4);
            x.x *= sc; x.y *= sc; x.z *= sc; x.w *= sc;
            y.x *= sc; y.y *= sc; y.z *= sc; y.w *= sc;
            uint4 hi, lo;
            split8(x, y, hi, lo);
            *reinterpret_cast<uint4*>(sm + dst + i * 16) = hi;
            *reinterpret_cast<uint4*>(sm + 2*FSM + dst + i * 16) = lo;
        }
    }
    __syncthreads();

    uint32_t qh[4][4], ql[4][4];
    {
        const uint32_t ra = (uint32_t)((w * 16 + (lane & 15)) * VRS) + (uint32_t)((lane >> 4) * 16);
        #pragma unroll
        for (int kb = 0; kb < 4; kb++) {
            ldm4(qh[kb], sKh + ra + (uint32_t)(kb * 32));
            ldm4(ql[kb], sVh + ra + (uint32_t)(kb * 32));
        }
    }

    float o[8][4];
    #pragma unroll
    for (int d = 0; d < 8; d++)
        #pragma unroll
        for (int e = 0; e < 4; e++) o[d][e] = 0.0f;
    float m0 = -INFINITY, m1 = -INFINITY, l0 = 0.0f, l1 = 0.0f;

    const uint32_t kAddrBase = (uint32_t)((lane & 7) * VRS + (lane >> 3) * 16);
    const uint32_t vAddrBase = (uint32_t)((lane & 15) * VRS) + (uint32_t)((lane >> 4) * 16);

    const int nkv = 2 * (qt + 1);
    for (int kt = 0; kt < nkv; kt++) {
        const int k0 = kt * 64;
        const int r = tid >> 2;
        const int cc = (tid & 3) * 16;
        float4 kr[4], vr[4];
        {
            const float* Kp = Kb + (size_t)(k0 + r) * DH + cc;
            const float* Vp = Vb + (size_t)(k0 + r) * DH + cc;
            #pragma unroll
            for (int i = 0; i < 4; i++) {
                kr[i] = *reinterpret_cast<const float4*>(Kp + i * 4);
                vr[i] = *reinterpret_cast<const float4*>(Vp + i * 4);
            }
        }
        __syncthreads();
        {
            uint32_t dst = (uint32_t)(r * VRS + (tid & 3) * 32);
            uint4 hi, lo;
            split8(kr[0], kr[1], hi, lo);
            *reinterpret_cast<uint4*>(sm + dst) = hi;
            *reinterpret_cast<uint4*>(sm + FSM + dst) = lo;
            split8(kr[2], kr[3], hi, lo);
            *reinterpret_cast<uint4*>(sm + dst + 16) = hi;
            *reinterpret_cast<uint4*>(sm + FSM + dst + 16) = lo;
            split8(vr[0], vr[1], hi, lo);
            *reinterpret_cast<uint4*>(sm + 2*FSM + dst) = hi;
            *reinterpret_cast<uint4*>(sm + 3*FSM + dst) = lo;
            split8(vr[2], vr[3], hi, lo);
            *reinterpret_cast<uint4*>(sm + 2*FSM + dst + 16) = hi;
            *reinterpret_cast<uint4*>(sm + 3*FSM + dst + 16) = lo;
        }
        __syncthreads();

        float s[8][4];
        #pragma unroll
        for (int jb = 0; jb < 8; jb++) {
            s[jb][0] = s[jb][1] = s[jb][2] = s[jb][3] = 0.0f;
            uint32_t khf[8], klf[8];
            const uint32_t ka = kAddrBase + (uint32_t)(jb * 8 * VRS);
            ldm4(&khf[0], sKh + ka);
            ldm4(&khf[4], sKh + ka + 64);
            ldm4(&klf[0], sKl + ka);
            ldm4(&klf[4], sKl + ka + 64);
            #pragma unroll
            for (int kb = 0; kb < 4; kb++) {
                mma16816(s[jb], qh[kb], &khf[kb * 2]);
                mma16816(s[jb], qh[kb], &klf[kb * 2]);
                mma16816(s[jb], ql[kb], &khf[kb * 2]);
            }
        }

        if (kt >= nkv - 2) {
            const int r0 = q0 + w * 16 + (lane >> 2);
            const int cb = k0 + (lane & 3) * 2;
            #pragma unroll
            for (int jb = 0; jb < 8; jb++) {
                const int c0 = cb + jb * 8;
                if (c0     > r0)     s[jb][0] = -INFINITY;
                if (c0 + 1 > r0)     s[jb][1] = -INFINITY;
                if (c0     > r0 + 8) s[jb][2] = -INFINITY;
                if (c0 + 1 > r0 + 8) s[jb][3] = -INFINITY;
            }
        }

        float nm0 = m0, nm1 = m1;
        #pragma unroll
        for (int jb = 0; jb < 8; jb++) {
            nm0 = fmaxf(nm0, fmaxf(s[jb][0], s[jb][1]));
            nm1 = fmaxf(nm1, fmaxf(s[jb][2], s[jb][3]));
        }
        nm0 = fmaxf(nm0, __shfl_xor_sync(0xFFFFFFFF, nm0, 1));
        nm0 = fmaxf(nm0, __shfl_xor_sync(0xFFFFFFFF, nm0, 2));
        nm1 = fmaxf(nm1, __shfl_xor_sync(0xFFFFFFFF, nm1, 1));
        nm1 = fmaxf(nm1, __shfl_xor_sync(0xFFFFFFFF, nm1, 2));
        const float c0 = fex2(m0 - nm0);
        const float c1 = fex2(m1 - nm1);
        m0 = nm0; m1 = nm1;

        float ps0 = 0.0f, ps1 = 0.0f;
        #pragma unroll
        for (int jb = 0; jb < 8; jb++) {
            s[jb][0] = fex2(s[jb][0] - nm0);
            s[jb][1] = fex2(s[jb][1] - nm0);
            s[jb][2] = fex2(s[jb][2] - nm1);
            s[jb][3] = fex2(s[jb][3] - nm1);
            ps0 += s[jb][0] + s[jb][1];
            ps1 += s[jb][2] + s[jb][3];
        }
        ps0 += __shfl_xor_sync(0xFFFFFFFF, ps0, 1);
        ps0 += __shfl_xor_sync(0xFFFFFFFF, ps0, 2);
        ps1 += __shfl_xor_sync(0xFFFFFFFF, ps1, 1);
        ps1 += __shfl_xor_sync(0xFFFFFFFF, ps1, 2);
        l0 = l0 * c0 + ps0;
        l1 = l1 * c1 + ps1;
        #pragma unroll
        for (int d = 0; d < 8; d++) {
            o[d][0] *= c0; o[d][1] *= c0;
            o[d][2] *= c1; o[d][3] *= c1;
        }

        #pragma unroll
        for (int kb = 0; kb < 4; kb++) {
            uint32_t ph[4], pl[4];
            ph[0] = split2(s[2*kb][0],   s[2*kb][1],   pl[0]);
            ph[1] = split2(s[2*kb][2],   s[2*kb][3],   pl[1]);
            ph[2] = split2(s[2*kb+1][0], s[2*kb+1][1], pl[2]);
            ph[3] = split2(s[2*kb+1][2], s[2*kb+1][3], pl[3]);
            const uint32_t va = vAddrBase + (uint32_t)(kb * 16 * VRS);
            #pragma unroll
            for (int dbp = 0; dbp < 4; dbp++) {
                uint32_t vh[4], vl[4];
                ldm4t(vh, sVh + va + (uint32_t)(dbp * 32));
                ldm4t(vl, sVl + va + (uint32_t)(dbp * 32));
                mma16816(o[dbp*2],     ph, &vh[0]);
                mma16816(o[dbp*2],     pl, &vh[0]);
                mma16816(o[dbp*2],     ph, &vl[0]);
                mma16816(o[dbp*2 + 1], ph, &vh[2]);
                mma16816(o[dbp*2 + 1], pl, &vh[2]);
                mma16816(o[dbp*2 + 1], ph, &vl[2]);
            }
        }
    }

    const float i0 = 1.0f / l0;
    const float i1 = 1.0f / l1;
    const int r0 = q0 + w * 16 + (lane >> 2);
    float* out0 = g_attn + ((size_t)(b * SS + r0)) * DMODEL + h * DH + (lane & 3) * 2;
    float* out1 = out0 + (size_t)8 * DMODEL;
    #pragma unroll
    for (int d = 0; d < 8; d++) {
        float2 v0, v1;
        v0.x = o[d][0] * i0; v0.y = o[d][1] * i0;
        v1.x = o[d][2] * i1; v1.y = o[d][3] * i1;
        *reinterpret_cast<float2*>(out0 + d * 8) = v0;
        *reinterpret_cast<float2*>(out1 + d * 8) = v1;
    }
}

// ---------------------------------------------------------------------------
extern "C" void kernel_launch(void* const* d_in, const int* in_sizes, int n_in,
                              void* d_out, int out_size)
{
    const float* X  = (const float*)d_in[0];
    const float* Wq = (const float*)d_in[1];
    const float* Wk = (const float*)d_in[2];
    const float* Wv = (const float*)d_in[3];
    const float* Wo = (const float*)d_in[4];
    const float* bo = (const float*)d_in[5];
    float* out = (float*)d_out;

    // 1. QKV projections (fp16 2-term HMMA) -> head-major scratch
    gemm_hmma<true><<<dim3(8, 32, 3), 128>>>(X, Wq, Wk, Wv, nullptr, nullptr);
    // 2. RoPE in-place on Q, K
    rope_kernel<<<(BB*NH*SS*32) / 256, 256>>>();
    // 3. Causal flash attention (HMMA bf16 3-term) -> g_attn [b, s, h*dh]
    flash_hmma<<<dim3(32, 16), 256>>>();
    // 4. Output projection + bias -> d_out
    gemm_hmma<false><<<dim3(8, 32, 1), 128>>>(nullptr, Wo, nullptr, nullptr, bo, out);
}

// round 15
// speedup vs baseline: 1.3049x; 1.0276x over previous
#include <cuda_runtime.h>
#include <cuda_bf16.h>
#include <cuda_fp16.h>
#include <math.h>
#include <stdint.h>

#define BB 2
#define SS 2048
#define DMODEL 1024
#define NH 16
#define DH 64
#define MM (BB*SS)

// Scratch (device globals: allocation-guard safe).
__device__ float g_q[BB*NH*SS*DH];
__device__ float g_k[BB*NH*SS*DH];
__device__ float g_v[BB*NH*SS*DH];
__device__ __align__(16) __half g_xh[MM*DMODEL];        // X as fp16
__device__ __align__(16) __half g_wh[4*DMODEL*DMODEL];  // W hi (q,k,v,o)
__device__ __align__(16) __half g_wl[4*DMODEL*DMODEL];  // W residual
__device__ __align__(16) __half g_ath[MM*DMODEL];       // attention out fp16

__device__ __forceinline__ float fex2(float x) {
    float y;
    asm("ex2.approx.ftz.f32 %0, %1;" : "=f"(y) : "f"(x));
    return y;
}
__device__ __forceinline__ uint32_t smem_u32(const void* p) {
    uint32_t a;
    asm("{ .reg .u64 t; cvta.to.shared.u64 t, %1; cvt.u32.u64 %0, t; }" : "=r"(a) : "l"(p));
    return a;
}
__device__ __forceinline__ void ldm4(uint32_t* r, uint32_t addr) {
    asm volatile("ldmatrix.sync.aligned.m8n8.x4.shared.b16 {%0,%1,%2,%3}, [%4];"
                 : "=r"(r[0]), "=r"(r[1]), "=r"(r[2]), "=r"(r[3]) : "r"(addr));
}
__device__ __forceinline__ void ldm4t(uint32_t* r, uint32_t addr) {
    asm volatile("ldmatrix.sync.aligned.m8n8.x4.trans.shared.b16 {%0,%1,%2,%3}, [%4];"
                 : "=r"(r[0]), "=r"(r[1]), "=r"(r[2]), "=r"(r[3]) : "r"(addr));
}
__device__ __forceinline__ void mma16816(float* c, const uint32_t* a, const uint32_t* b) {
    asm volatile(
        "mma.sync.aligned.m16n8k16.row.col.f32.bf16.bf16.f32 "
        "{%0,%1,%2,%3}, {%4,%5,%6,%7}, {%8,%9}, {%0,%1,%2,%3};"
        : "+f"(c[0]), "+f"(c[1]), "+f"(c[2]), "+f"(c[3])
        : "r"(a[0]), "r"(a[1]), "r"(a[2]), "r"(a[3]), "r"(b[0]), "r"(b[1]));
}
__device__ __forceinline__ void mma16816h(float* c, const uint32_t* a, const uint32_t* b) {
    asm volatile(
        "mma.sync.aligned.m16n8k16.row.col.f32.f16.f16.f32 "
        "{%0,%1,%2,%3}, {%4,%5,%6,%7}, {%8,%9}, {%0,%1,%2,%3};"
        : "+f"(c[0]), "+f"(c[1]), "+f"(c[2]), "+f"(c[3])
        : "r"(a[0]), "r"(a[1]), "r"(a[2]), "r"(a[3]), "r"(b[0]), "r"(b[1]));
}
__device__ __forceinline__ uint32_t split2(float x, float y, uint32_t& lop) {
    __nv_bfloat162 h = __floats2bfloat162_rn(x, y);
    float rx = x - __bfloat162float(h.x);
    float ry = y - __bfloat162float(h.y);
    __nv_bfloat162 l = __floats2bfloat162_rn(rx, ry);
    lop = *reinterpret_cast<uint32_t*>(&l);
    return *reinterpret_cast<uint32_t*>(&h);
}
__device__ __forceinline__ void split8(const float4& a, const float4& b,
                                       uint4& hi, uint4& lo) {
    hi.x = split2(a.x, a.y, lo.x);
    hi.y = split2(a.z, a.w, lo.y);
    hi.z = split2(b.x, b.y, lo.z);
    hi.w = split2(b.z, b.w, lo.w);
}
__device__ __forceinline__ uint32_t pack2h(float x, float y) {
    __half2 h = __floats2half2_rn(x, y);
    return *reinterpret_cast<uint32_t*>(&h);
}

// ======= one-time conversions (R8-validated: int offsets, globals indexed
// ONLY in device code — never pass __device__ symbols from host) =============
__global__ __launch_bounds__(256) void conv_h(const float4* __restrict__ src, int n4)
{
    int i = blockIdx.x * blockDim.x + threadIdx.x;
    if (i >= n4) return;
    float4 v = src[i];
    uint2 o;
    o.x = pack2h(v.x, v.y);
    o.y = pack2h(v.z, v.w);
    reinterpret_cast<uint2*>(g_xh)[i] = o;
}
__global__ __launch_bounds__(256) void conv_hl(const float4* __restrict__ src,
                                               int dst4, int n4)
{
    int i = blockIdx.x * blockDim.x + threadIdx.x;
    if (i >= n4) return;
    float4 v = src[i];
    __half2 h0 = __floats2half2_rn(v.x, v.y);
    __half2 h1 = __floats2half2_rn(v.z, v.w);
    __half2 l0 = __floats2half2_rn(v.x - __half2float(__low2half(h0)),
                                   v.y - __half2float(__high2half(h0)));
    __half2 l1 = __floats2half2_rn(v.z - __half2float(__low2half(h1)),
                                   v.w - __half2float(__high2half(h1)));
    uint2 oh, ol;
    oh.x = *reinterpret_cast<uint32_t*>(&h0); oh.y = *reinterpret_cast<uint32_t*>(&h1);
    ol.x = *reinterpret_cast<uint32_t*>(&l0); ol.y = *reinterpret_cast<uint32_t*>(&l1);
    reinterpret_cast<uint2*>(g_wh)[dst4 + i] = oh;
    reinterpret_cast<uint2*>(g_wl)[dst4 + i] = ol;
}

// ======== fp16 2-term GEMM: R11 skeleton, pre-converted operands ============
#define RS 80
#define OPB (128 * RS)   // 10240 B per operand tile; 3*OPB = 30720 B static

template<bool QKV>
__global__ __launch_bounds__(128, 2) void gemm_hmma(
    const float* __restrict__ bias, float* __restrict__ Oout)
{
    __shared__ uint8_t sm[3 * OPB];
    const uint32_t sb = smem_u32(sm);
    const uint32_t sAh = sb, sBh = sb + OPB, sBl = sb + 2*OPB;

    const int tid = threadIdx.x;
    const int lane = tid & 31;
    const int wid = tid >> 5;           // 0..3
    const int warp_m = wid >> 1;        // 0..1 -> 64 rows
    const int warp_n = wid & 1;         // 0..1 -> 64 cols
    const int zz = QKV ? (int)blockIdx.z : 3;
    const int m0 = blockIdx.y * 128;
    const int n0 = blockIdx.x * 128;

    const __half* A = QKV ? g_xh : g_ath;
    const __half* Bh = g_wh + (size_t)zz * DMODEL * DMODEL;
    const __half* Bl = g_wl + (size_t)zz * DMODEL * DMODEL;

    const int lrow = tid >> 2;          // 0..31 (rows lrow + 32p)
    const int c8 = tid & 3;             // 16B segment

    // fragment addressing (validated, RS=80)
    const int aRow = warp_m * 64 + (lane & 15);
    const uint32_t aByte = (uint32_t)((lane >> 4) * 16);
    const int bRow = warp_n * 64 + ((lane >> 4) * 8) + (lane & 7);
    const uint32_t bByte = (uint32_t)(((lane >> 3) & 1) * 16);

    float c[4][8][4];
    #pragma unroll
    for (int i = 0; i < 4; i++)
        #pragma unroll
        for (int j = 0; j < 8; j++)
            #pragma unroll
            for (int e = 0; e < 4; e++) c[i][j][e] = 0.0f;

    for (int ck = 0; ck < 32; ck++) {
        const int k0 = ck * 32;
        // LDG fp16 directly (no in-loop conversion)
        uint4 av[4], bhv[4], blv[4];
        #pragma unroll
        for (int p = 0; p < 4; p++) {
            av[p]  = *reinterpret_cast<const uint4*>(A  + (size_t)(m0 + lrow + 32*p) * DMODEL + k0 + c8 * 8);
            bhv[p] = *reinterpret_cast<const uint4*>(Bh + (size_t)(n0 + lrow + 32*p) * DMODEL + k0 + c8 * 8);
            blv[p] = *reinterpret_cast<const uint4*>(Bl + (size_t)(n0 + lrow + 32*p) * DMODEL + k0 + c8 * 8);
        }

        __syncthreads();  // previous iteration's ldmatrix reads done

        #pragma unroll
        for (int p = 0; p < 4; p++) {
            const uint32_t o = (uint32_t)((lrow + 32*p) * RS + c8 * 16);
            *(uint4*)(sm + o) = av[p];
            *(uint4*)(sm + OPB + o) = bhv[p];
            *(uint4*)(sm + 2*OPB + o) = blv[p];
        }
        __syncthreads();

        #pragma unroll
        for (int ks = 0; ks < 2; ks++) {
            const uint32_t kByte = (uint32_t)(ks * 32);
            uint32_t ah[4][4], bh[4][4], bl[4][4];
            #pragma unroll
            for (int i = 0; i < 4; i++)
                ldm4(ah[i], sAh + (uint32_t)((aRow + i * 16) * RS) + kByte + aByte);
            #pragma unroll
            for (int nb = 0; nb < 4; nb++)
                ldm4(bh[nb], sBh + (uint32_t)((bRow + nb * 16) * RS) + kByte + bByte);
            #pragma unroll
            for (int i = 0; i < 4; i++)
                #pragma unroll
                for (int j = 0; j < 8; j++)
                    mma16816h(c[i][j], ah[i], &bh[j >> 1][(j & 1) * 2]);
            #pragma unroll
            for (int nb = 0; nb < 4; nb++)
                ldm4(bl[nb], sBl + (uint32_t)((bRow + nb * 16) * RS) + kByte + bByte);
            #pragma unroll
            for (int i = 0; i < 4; i++)
                #pragma unroll
                for (int j = 0; j < 8; j++)
                    mma16816h(c[i][j], ah[i], &bl[j >> 1][(j & 1) * 2]);
        }
    }

    // ---- epilogue (R11-identical) ----
    const int mrow = m0 + warp_m * 64 + (lane >> 2);
    const int ncol = n0 + warp_n * 64 + (lane & 3) * 2;
    #pragma unroll
    for (int i = 0; i < 4; i++) {
        #pragma unroll
        for (int half = 0; half < 2; half++) {
            const int m = mrow + i * 16 + half * 8;
            #pragma unroll
            for (int j = 0; j < 8; j++) {
                const int n = ncol + j * 8;
                float2 v;
                v.x = c[i][j][half * 2 + 0];
                v.y = c[i][j][half * 2 + 1];
                if (QKV) {
                    float* O = (zz == 0) ? g_q : (zz == 1) ? g_k : g_v;
                    const int b = m >> 11;
                    const int s = m & (SS - 1);
                    const int h = n >> 6, d = n & 63;
                    *reinterpret_cast<float2*>(
                        O + (((size_t)(b * NH + h)) * SS + s) * DH + d) = v;
                } else {
                    v.x += bias[n];
                    v.y += bias[n + 1];
                    *reinterpret_cast<float2*>(Oout + (size_t)m * DMODEL + n) = v;
                }
            }
        }
    }
}

// =========================== RoPE (validated, unchanged) ====================
__global__ __launch_bounds__(256) void rope_kernel()
{
    int idx = blockIdx.x * blockDim.x + threadIdx.x;
    int d  = idx & 31;
    int s  = (idx >> 5) & (SS - 1);
    int bh = idx >> 16;
    size_t base = ((size_t)bh * SS + s) * DH;

    const float nl2 = -13.2877123795494f / 32.0f;
    float inv_freq = exp2f((float)d * nl2);
    float ang = (float)s * inv_freq;
    float sn, cs;
    sincosf(ang, &sn, &cs);

    float q1 = g_q[base + d], q2 = g_q[base + d + 32];
    g_q[base + d]      = q1 * cs - q2 * sn;
    g_q[base + d + 32] = q2 * cs + q1 * sn;

    float k1 = g_k[base + d], k2 = g_k[base + d + 32];
    g_k[base + d]      = k1 * cs - k2 * sn;
    g_k[base + d + 32] = k2 * cs + k1 * sn;
}

// ================== Flash attention (HMMA, validated) =======================
#define VRS 144
#define FSM (64 * VRS)

__global__ __launch_bounds__(256) void flash_hmma()
{
    __shared__ uint8_t sm[4 * FSM];
    const uint32_t sb = smem_u32(sm);
    const uint32_t sKh = sb, sKl = sb + FSM, sVh = sb + 2*FSM, sVl = sb + 3*FSM;

    const int bh = blockIdx.x;
    const int qt = (gridDim.y - 1) - blockIdx.y;
    const int q0 = qt * 128;
    const int tid = threadIdx.x;
    const int lane = tid & 31;
    const int w = tid >> 5;
    const int b = bh >> 4;
    const int h = bh & 15;

    const float* Qb = g_q + (size_t)bh * SS * DH;
    const float* Kb = g_k + (size_t)bh * SS * DH;
    const float* Vb = g_v + (size_t)bh * SS * DH;

    const float sc = 0.125f * 1.44269504088896f;

    {
        const int row = tid >> 1;
        const int half = tid & 1;
        const float* Qp = Qb + (size_t)(q0 + row) * DH + half * 32;
        uint32_t dst = (uint32_t)(row * VRS + half * 64);
        #pragma unroll
        for (int i = 0; i < 4; i++) {
            float4 x = *reinterpret_cast<const float4*>(Qp + i * 8);
            float4 y = *reinterpret_cast<const float4*>(Qp + i * 8 + 4);
            x.x *= sc; x.y *= sc; x.z *= sc; x.w *= sc;
            y.x *= sc; y.y *= sc; y.z *= sc; y.w *= sc;
            uint4 hi, lo;
            split8(x, y, hi, lo);
            *reinterpret_cast<uint4*>(sm + dst + i * 16) = hi;
            *reinterpret_cast<uint4*>(sm + 2*FSM + dst + i * 16) = lo;
        }
    }
    __syncthreads();

    uint32_t qh[4][4], ql[4][4];
    {
        const uint32_t ra = (uint32_t)((w * 16 + (lane & 15)) * VRS) + (uint32_t)((lane >> 4) * 16);
        #pragma unroll
        for (int kb = 0; kb < 4; kb++) {
            ldm4(qh[kb], sKh + ra + (uint32_t)(kb * 32));
            ldm4(ql[kb], sVh + ra + (uint32_t)(kb * 32));
        }
    }

    float o[8][4];
    #pragma unroll
    for (int d = 0; d < 8; d++)
        #pragma unroll
        for (int e = 0; e < 4; e++) o[d][e] = 0.0f;
    float m0 = -INFINITY, m1 = -INFINITY, l0 = 0.0f, l1 = 0.0f;

    const uint32_t kAddrBase = (uint32_t)((lane & 7) * VRS + (lane >> 3) * 16);
    const uint32_t vAddrBase = (uint32_t)((lane & 15) * VRS) + (uint32_t)((lane >> 4) * 16);

    const int nkv = 2 * (qt + 1);
    for (int kt = 0; kt < nkv; kt++) {
        const int k0 = kt * 64;
        const int r = tid >> 2;
        const int cc = (tid & 3) * 16;
        float4 kr[4], vr[4];
        {
            const float* Kp = Kb + (size_t)(k0 + r) * DH + cc;
            const float* Vp = Vb + (size_t)(k0 + r) * DH + cc;
            #pragma unroll
            for (int i = 0; i < 4; i++) {
                kr[i] = *reinterpret_cast<const float4*>(Kp + i * 4);
                vr[i] = *reinterpret_cast<const float4*>(Vp + i * 4);
            }
        }
        __syncthreads();
        {
            uint32_t dst = (uint32_t)(r * VRS + (tid & 3) * 32);
            uint4 hi, lo;
            split8(kr[0], kr[1], hi, lo);
            *reinterpret_cast<uint4*>(sm + dst) = hi;
            *reinterpret_cast<uint4*>(sm + FSM + dst) = lo;
            split8(kr[2], kr[3], hi, lo);
            *reinterpret_cast<uint4*>(sm + dst + 16) = hi;
            *reinterpret_cast<uint4*>(sm + FSM + dst + 16) = lo;
            split8(vr[0], vr[1], hi, lo);
            *reinterpret_cast<uint4*>(sm + 2*FSM + dst) = hi;
            *reinterpret_cast<uint4*>(sm + 3*FSM + dst) = lo;
            split8(vr[2], vr[3], hi, lo);
            *reinterpret_cast<uint4*>(sm + 2*FSM + dst + 16) = hi;
            *reinterpret_cast<uint4*>(sm + 3*FSM + dst + 16) = lo;
        }
        __syncthreads();

        float s[8][4];
        #pragma unroll
        for (int jb = 0; jb < 8; jb++) {
            s[jb][0] = s[jb][1] = s[jb][2] = s[jb][3] = 0.0f;
            uint32_t khf[8], klf[8];
            const uint32_t ka = kAddrBase + (uint32_t)(jb * 8 * VRS);
            ldm4(&khf[0], sKh + ka);
            ldm4(&khf[4], sKh + ka + 64);
            ldm4(&klf[0], sKl + ka);
            ldm4(&klf[4], sKl + ka + 64);
            #pragma unroll
            for (int kb = 0; kb < 4; kb++) {
                mma16816(s[jb], qh[kb], &khf[kb * 2]);
                mma16816(s[jb], qh[kb], &klf[kb * 2]);
                mma16816(s[jb], ql[kb], &khf[kb * 2]);
            }
        }

        if (kt >= nkv - 2) {
            const int r0 = q0 + w * 16 + (lane >> 2);
            const int cb = k0 + (lane & 3) * 2;
            #pragma unroll
            for (int jb = 0; jb < 8; jb++) {
                const int c0 = cb + jb * 8;
                if (c0     > r0)     s[jb][0] = -INFINITY;
                if (c0 + 1 > r0)     s[jb][1] = -INFINITY;
                if (c0     > r0 + 8) s[jb][2] = -INFINITY;
                if (c0 + 1 > r0 + 8) s[jb][3] = -INFINITY;
            }
        }

        float nm0 = m0, nm1 = m1;
        #pragma unroll
        for (int jb = 0; jb < 8; jb++) {
            nm0 = fmaxf(nm0, fmaxf(s[jb][0], s[jb][1]));
            nm1 = fmaxf(nm1, fmaxf(s[jb][2], s[jb][3]));
        }
        nm0 = fmaxf(nm0, __shfl_xor_sync(0xFFFFFFFF, nm0, 1));
        nm0 = fmaxf(nm0, __shfl_xor_sync(0xFFFFFFFF, nm0, 2));
        nm1 = fmaxf(nm1, __shfl_xor_sync(0xFFFFFFFF, nm1, 1));
        nm1 = fmaxf(nm1, __shfl_xor_sync(0xFFFFFFFF, nm1, 2));
        const float c0 = fex2(m0 - nm0);
        const float c1 = fex2(m1 - nm1);
        m0 = nm0; m1 = nm1;

        float ps0 = 0.0f, ps1 = 0.0f;
        #pragma unroll
        for (int jb = 0; jb < 8; jb++) {
            s[jb][0] = fex2(s[jb][0] - nm0);
            s[jb][1] = fex2(s[jb][1] - nm0);
            s[jb][2] = fex2(s[jb][2] - nm1);
            s[jb][3] = fex2(s[jb][3] - nm1);
            ps0 += s[jb][0] + s[jb][1];
            ps1 += s[jb][2] + s[jb][3];
        }
        ps0 += __shfl_xor_sync(0xFFFFFFFF, ps0, 1);
        ps0 += __shfl_xor_sync(0xFFFFFFFF, ps0, 2);
        ps1 += __shfl_xor_sync(0xFFFFFFFF, ps1, 1);
        ps1 += __shfl_xor_sync(0xFFFFFFFF, ps1, 2);
        l0 = l0 * c0 + ps0;
        l1 = l1 * c1 + ps1;
        #pragma unroll
        for (int d = 0; d < 8; d++) {
            o[d][0] *= c0; o[d][1] *= c0;
            o[d][2] *= c1; o[d][3] *= c1;
        }

        #pragma unroll
        for (int kb = 0; kb < 4; kb++) {
            uint32_t ph[4], pl[4];
            ph[0] = split2(s[2*kb][0],   s[2*kb][1],   pl[0]);
            ph[1] = split2(s[2*kb][2],   s[2*kb][3],   pl[1]);
            ph[2] = split2(s[2*kb+1][0], s[2*kb+1][1], pl[2]);
            ph[3] = split2(s[2*kb+1][2], s[2*kb+1][3], pl[3]);
            const uint32_t va = vAddrBase + (uint32_t)(kb * 16 * VRS);
            #pragma unroll
            for (int dbp = 0; dbp < 4; dbp++) {
                uint32_t vh[4], vl[4];
                ldm4t(vh, sVh + va + (uint32_t)(dbp * 32));
                ldm4t(vl, sVl + va + (uint32_t)(dbp * 32));
                mma16816(o[dbp*2],     ph, &vh[0]);
                mma16816(o[dbp*2],     pl, &vh[0]);
                mma16816(o[dbp*2],     ph, &vl[0]);
                mma16816(o[dbp*2 + 1], ph, &vh[2]);
                mma16816(o[dbp*2 + 1], pl, &vh[2]);
                mma16816(o[dbp*2 + 1], ph, &vl[2]);
            }
        }
    }

    // epilogue: normalize, write fp16 (identical rounding to R11's O-GEMM path)
    const float i0 = 1.0f / l0;
    const float i1 = 1.0f / l1;
    const int r0 = q0 + w * 16 + (lane >> 2);
    uint32_t* outH = reinterpret_cast<uint32_t*>(g_ath);
    const uint32_t ro = (uint32_t)(b * SS + r0) * (DMODEL/2) + (uint32_t)(h * (DH/2) + (lane & 3));
    #pragma unroll
    for (int d = 0; d < 8; d++) {
        outH[ro + d * 4] = pack2h(o[d][0] * i0, o[d][1] * i0);
        outH[ro + 8 * (DMODEL/2) + d * 4] = pack2h(o[d][2] * i1, o[d][3] * i1);
    }
}

// ---------------------------------------------------------------------------
extern "C" void kernel_launch(void* const* d_in, const int* in_sizes, int n_in,
                              void* d_out, int out_size)
{
    const float* X  = (const float*)d_in[0];
    const float* Wq = (const float*)d_in[1];
    const float* Wk = (const float*)d_in[2];
    const float* Wv = (const float*)d_in[3];
    const float* Wo = (const float*)d_in[4];
    const float* bo = (const float*)d_in[5];
    float* out = (float*)d_out;

    // 0. one-time conversions (integer offsets; globals touched only in device code)
    conv_h<<<4096, 256>>>((const float4*)X, 1048576);
    conv_hl<<<1024, 256>>>((const float4*)Wq, 0,      262144);
    conv_hl<<<1024, 256>>>((const float4*)Wk, 262144, 262144);
    conv_hl<<<1024, 256>>>((const float4*)Wv, 524288, 262144);
    conv_hl<<<1024, 256>>>((const float4*)Wo, 786432, 262144);
    // 1. QKV projections (fp16 2-term HMMA, pre-converted operands)
    gemm_hmma<true><<<dim3(8, 32, 3), 128>>>(nullptr, nullptr);
    // 2. RoPE in-place on Q, K
    rope_kernel<<<(BB*NH*SS*32) / 256, 256>>>();
    // 3. Causal flash attention (HMMA bf16 3-term) -> g_ath (fp16)
    flash_hmma<<<dim3(32, 16), 256>>>();
    // 4. Output projection + bias -> d_out
    gemm_hmma<false><<<dim3(8, 32, 1), 128>>>(bo, out);
}

// round 17
// speedup vs baseline: 1.3527x; 1.0366x over previous
#include <cuda_runtime.h>
#include <cuda_bf16.h>
#include <cuda_fp16.h>
#include <math.h>
#include <stdint.h>

#define BB 2
#define SS 2048
#define DMODEL 1024
#define NH 16
#define DH 64
#define MM (BB*SS)

// Scratch (device globals: allocation-guard safe).
__device__ float g_q[BB*NH*SS*DH];
__device__ float g_k[BB*NH*SS*DH];
__device__ float g_v[BB*NH*SS*DH];
__device__ __align__(16) __half g_xh[MM*DMODEL];        // X as fp16
__device__ __align__(16) __half g_wh[4*DMODEL*DMODEL];  // W hi (q,k,v,o)
__device__ __align__(16) __half g_wl[4*DMODEL*DMODEL];  // W residual
__device__ __align__(16) __half g_ath[MM*DMODEL];       // attention out fp16
// pre-split bf16 operands for flash (written by rope kernel)
__device__ __align__(16) __nv_bfloat16 g_qh[BB*NH*SS*DH];
__device__ __align__(16) __nv_bfloat16 g_ql[BB*NH*SS*DH];
__device__ __align__(16) __nv_bfloat16 g_kh[BB*NH*SS*DH];
__device__ __align__(16) __nv_bfloat16 g_kl[BB*NH*SS*DH];
__device__ __align__(16) __nv_bfloat16 g_vh[BB*NH*SS*DH];
__device__ __align__(16) __nv_bfloat16 g_vl[BB*NH*SS*DH];

__device__ __forceinline__ float fex2(float x) {
    float y;
    asm("ex2.approx.ftz.f32 %0, %1;" : "=f"(y) : "f"(x));
    return y;
}
__device__ __forceinline__ uint32_t smem_u32(const void* p) {
    uint32_t a;
    asm("{ .reg .u64 t; cvta.to.shared.u64 t, %1; cvt.u32.u64 %0, t; }" : "=r"(a) : "l"(p));
    return a;
}
__device__ __forceinline__ void ldm4(uint32_t* r, uint32_t addr) {
    asm volatile("ldmatrix.sync.aligned.m8n8.x4.shared.b16 {%0,%1,%2,%3}, [%4];"
                 : "=r"(r[0]), "=r"(r[1]), "=r"(r[2]), "=r"(r[3]) : "r"(addr));
}
__device__ __forceinline__ void ldm4t(uint32_t* r, uint32_t addr) {
    asm volatile("ldmatrix.sync.aligned.m8n8.x4.trans.shared.b16 {%0,%1,%2,%3}, [%4];"
                 : "=r"(r[0]), "=r"(r[1]), "=r"(r[2]), "=r"(r[3]) : "r"(addr));
}
__device__ __forceinline__ void mma16816(float* c, const uint32_t* a, const uint32_t* b) {
    asm volatile(
        "mma.sync.aligned.m16n8k16.row.col.f32.bf16.bf16.f32 "
        "{%0,%1,%2,%3}, {%4,%5,%6,%7}, {%8,%9}, {%0,%1,%2,%3};"
        : "+f"(c[0]), "+f"(c[1]), "+f"(c[2]), "+f"(c[3])
        : "r"(a[0]), "r"(a[1]), "r"(a[2]), "r"(a[3]), "r"(b[0]), "r"(b[1]));
}
__device__ __forceinline__ void mma16816h(float* c, const uint32_t* a, const uint32_t* b) {
    asm volatile(
        "mma.sync.aligned.m16n8k16.row.col.f32.f16.f16.f32 "
        "{%0,%1,%2,%3}, {%4,%5,%6,%7}, {%8,%9}, {%0,%1,%2,%3};"
        : "+f"(c[0]), "+f"(c[1]), "+f"(c[2]), "+f"(c[3])
        : "r"(a[0]), "r"(a[1]), "r"(a[2]), "r"(a[3]), "r"(b[0]), "r"(b[1]));
}
__device__ __forceinline__ uint32_t split2(float x, float y, uint32_t& lop) {
    __nv_bfloat162 h = __floats2bfloat162_rn(x, y);
    float rx = x - __bfloat162float(h.x);
    float ry = y - __bfloat162float(h.y);
    __nv_bfloat162 l = __floats2bfloat162_rn(rx, ry);
    lop = *reinterpret_cast<uint32_t*>(&l);
    return *reinterpret_cast<uint32_t*>(&h);
}
__device__ __forceinline__ uint32_t pack2h(float x, float y) {
    __half2 h = __floats2half2_rn(x, y);
    return *reinterpret_cast<uint32_t*>(&h);
}
__device__ __forceinline__ void splitbf(float x, __nv_bfloat16& h, __nv_bfloat16& l) {
    h = __float2bfloat16_rn(x);
    l = __float2bfloat16_rn(x - __bfloat162float(h));
}

// ======= one-time conversions (int offsets; globals device-side only) =======
__global__ __launch_bounds__(256) void conv_h(const float4* __restrict__ src, int n4)
{
    int i = blockIdx.x * blockDim.x + threadIdx.x;
    if (i >= n4) return;
    float4 v = src[i];
    uint2 o;
    o.x = pack2h(v.x, v.y);
    o.y = pack2h(v.z, v.w);
    reinterpret_cast<uint2*>(g_xh)[i] = o;
}
// all four weights in one launch: i in [0, 4*262144)
__global__ __launch_bounds__(256) void conv_w(
    const float4* __restrict__ wq, const float4* __restrict__ wk,
    const float4* __restrict__ wv, const float4* __restrict__ wo)
{
    int i = blockIdx.x * blockDim.x + threadIdx.x;   // < 1048576
    int sel = i >> 18;
    const float4* src = (sel == 0) ? wq : (sel == 1) ? wk : (sel == 2) ? wv : wo;
    float4 v = src[i & 262143];
    __half2 h0 = __floats2half2_rn(v.x, v.y);
    __half2 h1 = __floats2half2_rn(v.z, v.w);
    __half2 l0 = __floats2half2_rn(v.x - __half2float(__low2half(h0)),
                                   v.y - __half2float(__high2half(h0)));
    __half2 l1 = __floats2half2_rn(v.z - __half2float(__low2half(h1)),
                                   v.w - __half2float(__high2half(h1)));
    uint2 oh, ol;
    oh.x = *reinterpret_cast<uint32_t*>(&h0); oh.y = *reinterpret_cast<uint32_t*>(&h1);
    ol.x = *reinterpret_cast<uint32_t*>(&l0); ol.y = *reinterpret_cast<uint32_t*>(&l1);
    reinterpret_cast<uint2*>(g_wh)[i] = oh;
    reinterpret_cast<uint2*>(g_wl)[i] = ol;
}

// ======== fp16 2-term GEMM (R15-validated, unchanged) =======================
#define RS 80
#define OPB (128 * RS)

template<bool QKV>
__global__ __launch_bounds__(128, 2) void gemm_hmma(
    const float* __restrict__ bias, float* __restrict__ Oout)
{
    __shared__ uint8_t sm[3 * OPB];
    const uint32_t sb = smem_u32(sm);
    const uint32_t sAh = sb, sBh = sb + OPB, sBl = sb + 2*OPB;

    const int tid = threadIdx.x;
    const int lane = tid & 31;
    const int wid = tid >> 5;
    const int warp_m = wid >> 1;
    const int warp_n = wid & 1;
    const int zz = QKV ? (int)blockIdx.z : 3;
    const int m0 = blockIdx.y * 128;
    const int n0 = blockIdx.x * 128;

    const __half* A = QKV ? g_xh : g_ath;
    const __half* Bh = g_wh + (size_t)zz * DMODEL * DMODEL;
    const __half* Bl = g_wl + (size_t)zz * DMODEL * DMODEL;

    const int lrow = tid >> 2;
    const int c8 = tid & 3;

    const int aRow = warp_m * 64 + (lane & 15);
    const uint32_t aByte = (uint32_t)((lane >> 4) * 16);
    const int bRow = warp_n * 64 + ((lane >> 4) * 8) + (lane & 7);
    const uint32_t bByte = (uint32_t)(((lane >> 3) & 1) * 16);

    float c[4][8][4];
    #pragma unroll
    for (int i = 0; i < 4; i++)
        #pragma unroll
        for (int j = 0; j < 8; j++)
            #pragma unroll
            for (int e = 0; e < 4; e++) c[i][j][e] = 0.0f;

    for (int ck = 0; ck < 32; ck++) {
        const int k0 = ck * 32;
        uint4 av[4], bhv[4], blv[4];
        #pragma unroll
        for (int p = 0; p < 4; p++) {
            av[p]  = *reinterpret_cast<const uint4*>(A  + (size_t)(m0 + lrow + 32*p) * DMODEL + k0 + c8 * 8);
            bhv[p] = *reinterpret_cast<const uint4*>(Bh + (size_t)(n0 + lrow + 32*p) * DMODEL + k0 + c8 * 8);
            blv[p] = *reinterpret_cast<const uint4*>(Bl + (size_t)(n0 + lrow + 32*p) * DMODEL + k0 + c8 * 8);
        }

        __syncthreads();

        #pragma unroll
        for (int p = 0; p < 4; p++) {
            const uint32_t o = (uint32_t)((lrow + 32*p) * RS + c8 * 16);
            *(uint4*)(sm + o) = av[p];
            *(uint4*)(sm + OPB + o) = bhv[p];
            *(uint4*)(sm + 2*OPB + o) = blv[p];
        }
        __syncthreads();

        #pragma unroll
        for (int ks = 0; ks < 2; ks++) {
            const uint32_t kByte = (uint32_t)(ks * 32);
            uint32_t ah[4][4], bh[4][4], bl[4][4];
            #pragma unroll
            for (int i = 0; i < 4; i++)
                ldm4(ah[i], sAh + (uint32_t)((aRow + i * 16) * RS) + kByte + aByte);
            #pragma unroll
            for (int nb = 0; nb < 4; nb++)
                ldm4(bh[nb], sBh + (uint32_t)((bRow + nb * 16) * RS) + kByte + bByte);
            #pragma unroll
            for (int i = 0; i < 4; i++)
                #pragma unroll
                for (int j = 0; j < 8; j++)
                    mma16816h(c[i][j], ah[i], &bh[j >> 1][(j & 1) * 2]);
            #pragma unroll
            for (int nb = 0; nb < 4; nb++)
                ldm4(bl[nb], sBl + (uint32_t)((bRow + nb * 16) * RS) + kByte + bByte);
            #pragma unroll
            for (int i = 0; i < 4; i++)
                #pragma unroll
                for (int j = 0; j < 8; j++)
                    mma16816h(c[i][j], ah[i], &bl[j >> 1][(j & 1) * 2]);
        }
    }

    const int mrow = m0 + warp_m * 64 + (lane >> 2);
    const int ncol = n0 + warp_n * 64 + (lane & 3) * 2;
    #pragma unroll
    for (int i = 0; i < 4; i++) {
        #pragma unroll
        for (int half = 0; half < 2; half++) {
            const int m = mrow + i * 16 + half * 8;
            #pragma unroll
            for (int j = 0; j < 8; j++) {
                const int n = ncol + j * 8;
                float2 v;
                v.x = c[i][j][half * 2 + 0];
                v.y = c[i][j][half * 2 + 1];
                if (QKV) {
                    float* O = (zz == 0) ? g_q : (zz == 1) ? g_k : g_v;
                    const int b = m >> 11;
                    const int s = m & (SS - 1);
                    const int h = n >> 6, d = n & 63;
                    *reinterpret_cast<float2*>(
                        O + (((size_t)(b * NH + h)) * SS + s) * DH + d) = v;
                } else {
                    v.x += bias[n];
                    v.y += bias[n + 1];
                    *reinterpret_cast<float2*>(Oout + (size_t)m * DMODEL + n) = v;
                }
            }
        }
    }
}

// ====== RoPE + split: rotate Q/K, write pre-scaled bf16 hi/lo; split V ======
__global__ __launch_bounds__(256) void rope_split_kernel()
{
    int idx = blockIdx.x * blockDim.x + threadIdx.x;
    int d  = idx & 31;
    int s  = (idx >> 5) & (SS - 1);
    int bh = idx >> 16;
    size_t base = ((size_t)bh * SS + s) * DH;

    const float nl2 = -13.2877123795494f / 32.0f;
    float inv_freq = exp2f((float)d * nl2);
    float ang = (float)s * inv_freq;
    float sn, cs;
    sincosf(ang, &sn, &cs);

    const float sc = 0.125f * 1.44269504088896f;   // folded into Q (as flash did)

    float q1 = g_q[base + d], q2 = g_q[base + d + 32];
    float qr1 = (q1 * cs - q2 * sn) * sc;
    float qr2 = (q2 * cs + q1 * sn) * sc;
    splitbf(qr1, g_qh[base + d],      g_ql[base + d]);
    splitbf(qr2, g_qh[base + d + 32], g_ql[base + d + 32]);

    float k1 = g_k[base + d], k2 = g_k[base + d + 32];
    float kr1 = k1 * cs - k2 * sn;
    float kr2 = k2 * cs + k1 * sn;
    splitbf(kr1, g_kh[base + d],      g_kl[base + d]);
    splitbf(kr2, g_kh[base + d + 32], g_kl[base + d + 32]);

    float v1 = g_v[base + d], v2 = g_v[base + d + 32];
    splitbf(v1, g_vh[base + d],      g_vl[base + d]);
    splitbf(v2, g_vh[base + d + 32], g_vl[base + d + 32]);
}

// ================== Flash attention (pre-split bf16 operands) ===============
#define VRS 144
#define FSM (64 * VRS)

__global__ __launch_bounds__(256) void flash_hmma()
{
    __shared__ uint8_t sm[4 * FSM];
    const uint32_t sb = smem_u32(sm);
    const uint32_t sKh = sb, sKl = sb + FSM, sVh = sb + 2*FSM, sVl = sb + 3*FSM;

    const int bh = blockIdx.x;
    const int qt = (gridDim.y - 1) - blockIdx.y;
    const int q0 = qt * 128;
    const int tid = threadIdx.x;
    const int lane = tid & 31;
    const int w = tid >> 5;
    const int b = bh >> 4;
    const int h = bh & 15;

    const size_t bhOff = (size_t)bh * SS * DH;

    // ---- stage Q hi/lo (pre-scaled, pre-split) ----
    {
        const int row = tid >> 1;
        const int half = tid & 1;
        const size_t src = bhOff + (size_t)(q0 + row) * DH + half * 32;
        const uint32_t dst = (uint32_t)(row * VRS + half * 64);
        #pragma unroll
        for (int i = 0; i < 4; i++) {
            *reinterpret_cast<uint4*>(sm + dst + i * 16) =
                *reinterpret_cast<const uint4*>(g_qh + src + i * 8);
            *reinterpret_cast<uint4*>(sm + 2*FSM + dst + i * 16) =
                *reinterpret_cast<const uint4*>(g_ql + src + i * 8);
        }
    }
    __syncthreads();

    uint32_t qh[4][4], ql[4][4];
    {
        const uint32_t ra = (uint32_t)((w * 16 + (lane & 15)) * VRS) + (uint32_t)((lane >> 4) * 16);
        #pragma unroll
        for (int kb = 0; kb < 4; kb++) {
            ldm4(qh[kb], sKh + ra + (uint32_t)(kb * 32));
            ldm4(ql[kb], sVh + ra + (uint32_t)(kb * 32));
        }
    }

    float o[8][4];
    #pragma unroll
    for (int d = 0; d < 8; d++)
        #pragma unroll
        for (int e = 0; e < 4; e++) o[d][e] = 0.0f;
    float m0 = -INFINITY, m1 = -INFINITY, l0 = 0.0f, l1 = 0.0f;

    const uint32_t kAddrBase = (uint32_t)((lane & 7) * VRS + (lane >> 3) * 16);
    const uint32_t vAddrBase = (uint32_t)((lane & 15) * VRS) + (uint32_t)((lane >> 4) * 16);

    const int nkv = 2 * (qt + 1);
    for (int kt = 0; kt < nkv; kt++) {
        const int k0 = kt * 64;
        const int r = tid >> 2;                 // 0..63
        const int ce = (tid & 3) * 16;          // element offset within row
        const size_t src = bhOff + (size_t)(k0 + r) * DH + ce;
        uint4 khv0, khv1, klv0, klv1, vhv0, vhv1, vlv0, vlv1;
        khv0 = *reinterpret_cast<const uint4*>(g_kh + src);
        khv1 = *reinterpret_cast<const uint4*>(g_kh + src + 8);
        klv0 = *reinterpret_cast<const uint4*>(g_kl + src);
        klv1 = *reinterpret_cast<const uint4*>(g_kl + src + 8);
        vhv0 = *reinterpret_cast<const uint4*>(g_vh + src);
        vhv1 = *reinterpret_cast<const uint4*>(g_vh + src + 8);
        vlv0 = *reinterpret_cast<const uint4*>(g_vl + src);
        vlv1 = *reinterpret_cast<const uint4*>(g_vl + src + 8);

        __syncthreads();   // prior iteration's ldmatrix reads complete
        {
            const uint32_t dst = (uint32_t)(r * VRS + (tid & 3) * 32);
            *reinterpret_cast<uint4*>(sm + dst) = khv0;
            *reinterpret_cast<uint4*>(sm + dst + 16) = khv1;
            *reinterpret_cast<uint4*>(sm + FSM + dst) = klv0;
            *reinterpret_cast<uint4*>(sm + FSM + dst + 16) = klv1;
            *reinterpret_cast<uint4*>(sm + 2*FSM + dst) = vhv0;
            *reinterpret_cast<uint4*>(sm + 2*FSM + dst + 16) = vhv1;
            *reinterpret_cast<uint4*>(sm + 3*FSM + dst) = vlv0;
            *reinterpret_cast<uint4*>(sm + 3*FSM + dst + 16) = vlv1;
        }
        __syncthreads();

        float s[8][4];
        #pragma unroll
        for (int jb = 0; jb < 8; jb++) {
            s[jb][0] = s[jb][1] = s[jb][2] = s[jb][3] = 0.0f;
            uint32_t khf[8], klf[8];
            const uint32_t ka = kAddrBase + (uint32_t)(jb * 8 * VRS);
            ldm4(&khf[0], sKh + ka);
            ldm4(&khf[4], sKh + ka + 64);
            ldm4(&klf[0], sKl + ka);
            ldm4(&klf[4], sKl + ka + 64);
            #pragma unroll
            for (int kb = 0; kb < 4; kb++) {
                mma16816(s[jb], qh[kb], &khf[kb * 2]);
                mma16816(s[jb], qh[kb], &klf[kb * 2]);
                mma16816(s[jb], ql[kb], &khf[kb * 2]);
            }
        }

        if (kt >= nkv - 2) {
            const int r0 = q0 + w * 16 + (lane >> 2);
            const int cb = k0 + (lane & 3) * 2;
            #pragma unroll
            for (int jb = 0; jb < 8; jb++) {
                const int c0 = cb + jb * 8;
                if (c0     > r0)     s[jb][0] = -INFINITY;
                if (c0 + 1 > r0)     s[jb][1] = -INFINITY;
                if (c0     > r0 + 8) s[jb][2] = -INFINITY;
                if (c0 + 1 > r0 + 8) s[jb][3] = -INFINITY;
            }
        }

        float nm0 = m0, nm1 = m1;
        #pragma unroll
        for (int jb = 0; jb < 8; jb++) {
            nm0 = fmaxf(nm0, fmaxf(s[jb][0], s[jb][1]));
            nm1 = fmaxf(nm1, fmaxf(s[jb][2], s[jb][3]));
        }
        nm0 = fmaxf(nm0, __shfl_xor_sync(0xFFFFFFFF, nm0, 1));
        nm0 = fmaxf(nm0, __shfl_xor_sync(0xFFFFFFFF, nm0, 2));
        nm1 = fmaxf(nm1, __shfl_xor_sync(0xFFFFFFFF, nm1, 1));
        nm1 = fmaxf(nm1, __shfl_xor_sync(0xFFFFFFFF, nm1, 2));
        const float c0 = fex2(m0 - nm0);
        const float c1 = fex2(m1 - nm1);
        m0 = nm0; m1 = nm1;

        float ps0 = 0.0f, ps1 = 0.0f;
        #pragma unroll
        for (int jb = 0; jb < 8; jb++) {
            s[jb][0] = fex2(s[jb][0] - nm0);
            s[jb][1] = fex2(s[jb][1] - nm0);
            s[jb][2] = fex2(s[jb][2] - nm1);
            s[jb][3] = fex2(s[jb][3] - nm1);
            ps0 += s[jb][0] + s[jb][1];
            ps1 += s[jb][2] + s[jb][3];
        }
        ps0 += __shfl_xor_sync(0xFFFFFFFF, ps0, 1);
        ps0 += __shfl_xor_sync(0xFFFFFFFF, ps0, 2);
        ps1 += __shfl_xor_sync(0xFFFFFFFF, ps1, 1);
        ps1 += __shfl_xor_sync(0xFFFFFFFF, ps1, 2);
        l0 = l0 * c0 + ps0;
        l1 = l1 * c1 + ps1;
        #pragma unroll
        for (int d = 0; d < 8; d++) {
            o[d][0] *= c0; o[d][1] *= c0;
            o[d][2] *= c1; o[d][3] *= c1;
        }

        #pragma unroll
        for (int kb = 0; kb < 4; kb++) {
            uint32_t ph[4], pl[4];
            ph[0] = split2(s[2*kb][0],   s[2*kb][1],   pl[0]);
            ph[1] = split2(s[2*kb][2],   s[2*kb][3],   pl[1]);
            ph[2] = split2(s[2*kb+1][0], s[2*kb+1][1], pl[2]);
            ph[3] = split2(s[2*kb+1][2], s[2*kb+1][3], pl[3]);
            const uint32_t va = vAddrBase + (uint32_t)(kb * 16 * VRS);
            #pragma unroll
            for (int dbp = 0; dbp < 4; dbp++) {
                uint32_t vh[4], vl[4];
                ldm4t(vh, sVh + va + (uint32_t)(dbp * 32));
                ldm4t(vl, sVl + va + (uint32_t)(dbp * 32));
                mma16816(o[dbp*2],     ph, &vh[0]);
                mma16816(o[dbp*2],     pl, &vh[0]);
                mma16816(o[dbp*2],     ph, &vl[0]);
                mma16816(o[dbp*2 + 1], ph, &vh[2]);
                mma16816(o[dbp*2 + 1], pl, &vh[2]);
                mma16816(o[dbp*2 + 1], ph, &vl[2]);
            }
        }
    }

    // epilogue: normalize, write fp16
    const float i0 = 1.0f / l0;
    const float i1 = 1.0f / l1;
    const int r0 = q0 + w * 16 + (lane >> 2);
    uint32_t* outH = reinterpret_cast<uint32_t*>(g_ath);
    const uint32_t ro = (uint32_t)(b * SS + r0) * (DMODEL/2) + (uint32_t)(h * (DH/2) + (lane & 3));
    #pragma unroll
    for (int d = 0; d < 8; d++) {
        outH[ro + d * 4] = pack2h(o[d][0] * i0, o[d][1] * i0);
        outH[ro + 8 * (DMODEL/2) + d * 4] = pack2h(o[d][2] * i1, o[d][3] * i1);
    }
}

// ---------------------------------------------------------------------------
extern "C" void kernel_launch(void* const* d_in, const int* in_sizes, int n_in,
                              void* d_out, int out_size)
{
    const float* X  = (const float*)d_in[0];
    const float* Wq = (const float*)d_in[1];
    const float* Wk = (const float*)d_in[2];
    const float* Wv = (const float*)d_in[3];
    const float* Wo = (const float*)d_in[4];
    const float* bo = (const float*)d_in[5];
    float* out = (float*)d_out;

    // 0. one-time conversions
    conv_h<<<4096, 256>>>((const float4*)X, 1048576);
    conv_w<<<4096, 256>>>((const float4*)Wq, (const float4*)Wk,
                          (const float4*)Wv, (const float4*)Wo);
    // 1. QKV projections (fp16 2-term HMMA, pre-converted operands)
    gemm_hmma<true><<<dim3(8, 32, 3), 128>>>(nullptr, nullptr);
    // 2. RoPE + bf16 hi/lo split of Q, K, V
    rope_split_kernel<<<(BB*NH*SS*32) / 256, 256>>>();
    // 3. Causal flash attention (HMMA bf16 3-term, pre-split operands)
    flash_hmma<<<dim3(32, 16), 256>>>();
    // 4. Output projection + bias -> d_out
    gemm_hmma<false><<<dim3(8, 32, 1), 128>>>(bo, out);
}